// round 7
// baseline (speedup 1.0000x reference)
#include <cuda_runtime.h>
#include <cuda_fp16.h>
#include <math.h>
#include <stdint.h>

#define SEQ   4096
#define HDIM  4096
#define INNER 4096
#define NH    32
#define HD    128
#define BLK   256
#define NB    16
#define QKVW  12288
#define EPS_RMS 1e-5f

#define GK    4096          // shared K dim of all three GEMMs
#define BM    128
#define BN    128
#define BK    64
#define NTHR  128
#define KTILES (GK / BK)    // 64
#define KPADH 72            // 64 + 8 halfs pad (144B row stride, conflict-free)
#define STGH_A (128 * KPADH)            // halfs per operand per stage (9216)
#define STAGE_BYTES (2 * STGH_A * 2)    // A + B bytes = 36864
#define NSTG  3
#define GEMM_SMEM (NSTG * STAGE_BYTES)  // 110592 -> 2 CTAs/SM

// ---------------- scratch ----------------
__device__ float  g_qkv[(size_t)SEQ * QKVW];      // fp32 silu(x@w_qkv^T) for attention
__device__ float  g_hidden[(size_t)SEQ * INNER];  // attention output
__device__ float  g_gate[(size_t)SEQ * INNER];    // sigmoid(x@w_gate^T)
__device__ float  g_S[(size_t)NH * NB * HD * HD];
__device__ float  g_kvst[(size_t)NH * NB * HD * HD];
__device__ __half g_xh[(size_t)SEQ * HDIM];       // fp16 inputs for GEMMs
__device__ __half g_wqkvh[(size_t)QKVW * HDIM];
__device__ __half g_wgateh[(size_t)INNER * HDIM];
__device__ __half g_wouth[(size_t)HDIM * INNER];
__device__ __half g_ghalf[(size_t)SEQ * INNER];   // fp16 (gate*normed) for GEMM3

// ---------------- helpers ----------------
__device__ __forceinline__ uint32_t smem_u32(const void* p) {
    uint32_t a;
    asm("{ .reg .u64 t; cvta.to.shared.u64 t, %1; cvt.u32.u64 %0, t; }" : "=r"(a) : "l"(p));
    return a;
}

__device__ __forceinline__ void cp_async16(uint32_t dst, const void* src) {
    asm volatile("cp.async.cg.shared.global [%0], [%1], 16;" :: "r"(dst), "l"(src));
}
#define CP_COMMIT() asm volatile("cp.async.commit_group;" ::: "memory")
#define CP_WAIT(n)  asm volatile("cp.async.wait_group %0;" :: "n"(n) : "memory")

__device__ __forceinline__ void ldsm_x4(uint32_t& r0, uint32_t& r1, uint32_t& r2, uint32_t& r3,
                                        uint32_t addr) {
    asm volatile("ldmatrix.sync.aligned.m8n8.x4.shared.b16 {%0,%1,%2,%3}, [%4];"
        : "=r"(r0), "=r"(r1), "=r"(r2), "=r"(r3) : "r"(addr));
}

__device__ __forceinline__ void mma_f16(float* c, const uint32_t* a, const uint32_t* b) {
    asm volatile(
        "mma.sync.aligned.m16n8k16.row.col.f32.f16.f16.f32 "
        "{%0,%1,%2,%3}, {%4,%5,%6,%7}, {%8,%9}, {%0,%1,%2,%3};"
        : "+f"(c[0]), "+f"(c[1]), "+f"(c[2]), "+f"(c[3])
        : "r"(a[0]), "r"(a[1]), "r"(a[2]), "r"(a[3]), "r"(b[0]), "r"(b[1]));
}

#define EPI_NONE 0
#define EPI_SILU 1
#define EPI_SIGM 2
template <int EPI>
__device__ __forceinline__ float epi(float v) {
    if (EPI == EPI_SILU) return v / (1.0f + expf(-v));
    if (EPI == EPI_SIGM) return 1.0f / (1.0f + expf(-v));
    return v;
}

// fp32 -> fp16 conversion kernel: each thread converts 8 floats -> 16B store
__global__ __launch_bounds__(256)
void cvt_f16_kernel(const float* __restrict__ in, __half* __restrict__ out, int n8) {
    int i = blockIdx.x * 256 + threadIdx.x;
    if (i < n8) {
        float4 v0 = ((const float4*)in)[i * 2];
        float4 v1 = ((const float4*)in)[i * 2 + 1];
        __half2 h0 = __floats2half2_rn(v0.x, v0.y);
        __half2 h1 = __floats2half2_rn(v0.z, v0.w);
        __half2 h2 = __floats2half2_rn(v1.x, v1.y);
        __half2 h3 = __floats2half2_rn(v1.z, v1.w);
        uint4 o;
        o.x = *(uint32_t*)&h0; o.y = *(uint32_t*)&h1;
        o.z = *(uint32_t*)&h2; o.w = *(uint32_t*)&h3;
        ((uint4*)out)[i] = o;
    }
}

// ---------------- fp16 mma.sync GEMM with ldmatrix ----------------
// C[m][n] = epi(sum_k A[m][k]*B[n][k]); CTA 128x128, 4 warps (warp 64x64), BK=64, 3 stages.
__device__ __forceinline__ void g_load_stage(uint32_t sbase, int slot, int s,
                                             const __half* __restrict__ Ab,
                                             const __half* __restrict__ Bb, int t)
{
    const uint32_t stA = sbase + slot * STAGE_BYTES;
    const uint32_t stB = stA + STGH_A * 2;
    const __half* ga = Ab + (size_t)s * BK;
    const __half* gb = Bb + (size_t)s * BK;
#pragma unroll
    for (int i = 0; i < 8; ++i) {                 // A: 128 rows x 8 chunks of 8 halfs
        int id = t + NTHR * i;
        int row = id >> 3, c = id & 7;
        cp_async16(stA + (row * KPADH + c * 8) * 2, ga + (size_t)row * GK + c * 8);
    }
#pragma unroll
    for (int i = 0; i < 8; ++i) {                 // B: 128 rows x 8 chunks
        int id = t + NTHR * i;
        int row = id >> 3, c = id & 7;
        cp_async16(stB + (row * KPADH + c * 8) * 2, gb + (size_t)row * GK + c * 8);
    }
}

template <int EPI>
__global__ __launch_bounds__(NTHR, 2)
void gemm_mma(const __half* __restrict__ A, const __half* __restrict__ B,
              float* __restrict__ C, int Ntot)
{
    extern __shared__ __align__(128) __half smem[];
    const uint32_t sbase = smem_u32(smem);
    const int t    = threadIdx.x;
    const int wid  = t >> 5;
    const int lane = t & 31;

    // CTA raster swizzle: chunks of 16 m-tiles, m fastest within chunk.
    const int nbx = gridDim.x;                    // n tiles
    const int bid = blockIdx.y * nbx + blockIdx.x;
    const int per_chunk = 16 * nbx;
    const int chunk = bid / per_chunk;
    const int rem   = bid % per_chunk;
    const int m_t   = chunk * 16 + (rem % 16);
    const int n_t   = rem / 16;
    const int bm = m_t * BM;
    const int bn = n_t * BN;

    const __half* Ab = A + (size_t)bm * GK;
    const __half* Bb = B + (size_t)bn * GK;

    const int wm = (wid & 1) * 64;        // warp row offset (0,64)
    const int wn = (wid >> 1) * 64;       // warp col offset (0,64)
    const int r  = lane >> 2;             // 0..7
    const int q  = lane & 3;              // 0..3

    // ldmatrix per-lane addressing: row = (lane&7) + ((lane>>3)&1)*8, col = (lane>>4)*8
    const int lrow = (lane & 7) + ((lane >> 3) & 1) * 8;
    const int lcol = (lane >> 4) * 8;

    float c[4][8][4];
#pragma unroll
    for (int i = 0; i < 4; ++i)
#pragma unroll
        for (int j = 0; j < 8; ++j)
#pragma unroll
            for (int p = 0; p < 4; ++p) c[i][j][p] = 0.0f;

    g_load_stage(sbase, 0, 0, Ab, Bb, t); CP_COMMIT();
    g_load_stage(sbase, 1, 1, Ab, Bb, t); CP_COMMIT();

    for (int s = 0; s < KTILES; ++s) {
        const int slot = s % NSTG;
        CP_WAIT(1);
        __syncthreads();

        if (s + 2 < KTILES) {
            g_load_stage(sbase, (s + 2) % NSTG, s + 2, Ab, Bb, t);
        }
        CP_COMMIT();

        const uint32_t sA = sbase + slot * STAGE_BYTES;
        const uint32_t sB = sA + STGH_A * 2;

#pragma unroll
        for (int ks = 0; ks < 4; ++ks) {          // 4 k16 slices per BK=64
            const int k0 = ks * 16;
            uint32_t af[4][4], bf[8][2];
            // A: four m16k16 tiles via ldmatrix.x4 (blocks: m0k0, m8k0, m0k8, m8k8)
#pragma unroll
            for (int i = 0; i < 4; ++i) {
                uint32_t addr = sA + ((wm + i * 16 + lrow) * KPADH + k0 + lcol) * 2;
                ldsm_x4(af[i][0], af[i][1], af[i][2], af[i][3], addr);
            }
            // B: four n16k16 tiles; regs map to (bf[2jj][0], bf[2jj+1][0], bf[2jj][1], bf[2jj+1][1])
#pragma unroll
            for (int jj = 0; jj < 4; ++jj) {
                uint32_t addr = sB + ((wn + jj * 16 + lrow) * KPADH + k0 + lcol) * 2;
                ldsm_x4(bf[2 * jj][0], bf[2 * jj + 1][0], bf[2 * jj][1], bf[2 * jj + 1][1], addr);
            }
#pragma unroll
            for (int i = 0; i < 4; ++i)
#pragma unroll
                for (int j = 0; j < 8; ++j)
                    mma_f16(c[i][j], af[i], bf[j]);
        }
    }

    // epilogue (c0,c1 -> row r; c2,c3 -> row r+8; cols 2q,2q+1)
#pragma unroll
    for (int i = 0; i < 4; ++i) {
        const int row0 = bm + wm + i * 16 + r;
#pragma unroll
        for (int j = 0; j < 8; ++j) {
            const int col = bn + wn + j * 8 + 2 * q;
            float2 v0 = make_float2(epi<EPI>(c[i][j][0]), epi<EPI>(c[i][j][1]));
            float2 v1 = make_float2(epi<EPI>(c[i][j][2]), epi<EPI>(c[i][j][3]));
            *(float2*)(C + (size_t)row0 * Ntot + col)       = v0;
            *(float2*)(C + (size_t)(row0 + 8) * Ntot + col) = v1;
        }
    }
}

// ---------------- attention stage A ----------------
__global__ __launch_bounds__(256)
void attn_kvblocks(const float* __restrict__ slope)
{
    const int b = blockIdx.x;
    const int h = blockIdx.y;
    const float s = slope[h];

    __shared__ float Ks[8][128];
    __shared__ float Vs[8][128];

    const int t  = threadIdx.x;
    const int ty = t >> 4, tx = t & 15;
    const int d0 = ty * 8, e0 = tx * 8;
    const int il = t >> 5;
    const int c4 = (t & 31) * 4;

    const float* kbase = g_qkv + (size_t)(b * BLK) * QKVW + h * 384 + 128;
    const float* vbase = kbase + 128;

    float acc[8][8];
#pragma unroll
    for (int i = 0; i < 8; ++i)
#pragma unroll
        for (int j = 0; j < 8; ++j) acc[i][j] = 0.0f;

    for (int ic = 0; ic < 32; ++ic) {
        const int i = ic * 8 + il;
        const float kd = expf(-s * (float)(255 - i));
        float4 k4 = *(const float4*)(kbase + (size_t)i * QKVW + c4);
        float4 v4 = *(const float4*)(vbase + (size_t)i * QKVW + c4);
        __syncthreads();
        Ks[il][c4 + 0] = k4.x * kd; Ks[il][c4 + 1] = k4.y * kd;
        Ks[il][c4 + 2] = k4.z * kd; Ks[il][c4 + 3] = k4.w * kd;
        *(float4*)&Vs[il][c4] = v4;
        __syncthreads();
#pragma unroll
        for (int ii = 0; ii < 8; ++ii) {
            float4 a0 = *(const float4*)&Ks[ii][d0];
            float4 a1 = *(const float4*)&Ks[ii][d0 + 4];
            float4 b0 = *(const float4*)&Vs[ii][e0];
            float4 b1 = *(const float4*)&Vs[ii][e0 + 4];
            float av[8] = {a0.x, a0.y, a0.z, a0.w, a1.x, a1.y, a1.z, a1.w};
            float bv[8] = {b0.x, b0.y, b0.z, b0.w, b1.x, b1.y, b1.z, b1.w};
#pragma unroll
            for (int i2 = 0; i2 < 8; ++i2)
#pragma unroll
                for (int j = 0; j < 8; ++j) acc[i2][j] += av[i2] * bv[j];
        }
    }

    float* Sp = g_S + (size_t)(h * NB + b) * HD * HD;
#pragma unroll
    for (int i = 0; i < 8; ++i) {
        *(float4*)&Sp[(size_t)(d0 + i) * HD + e0]     = make_float4(acc[i][0], acc[i][1], acc[i][2], acc[i][3]);
        *(float4*)&Sp[(size_t)(d0 + i) * HD + e0 + 4] = make_float4(acc[i][4], acc[i][5], acc[i][6], acc[i][7]);
    }
}

// ---------------- attention stage B ----------------
__global__ void attn_scan(const float* __restrict__ kv_cache, const float* __restrict__ slope)
{
    const int g = blockIdx.x * 256 + threadIdx.x;
    const int h = g >> 14;
    const int e = g & 16383;
    const float dec = expf(-slope[h] * 256.0f);
    float c = kv_cache[(size_t)h * 16384 + e];
    const size_t base = (size_t)h * NB * 16384 + e;
#pragma unroll
    for (int b = 0; b < NB; ++b) {
        g_kvst[base + (size_t)b * 16384] = c;
        c = dec * c + g_S[base + (size_t)b * 16384];
    }
}

// ---------------- attention stage C1 ----------------
__global__ __launch_bounds__(512)
void attn_ointer(const float* __restrict__ slope)
{
    const int b = blockIdx.x;
    const int h = blockIdx.y;
    const float s = slope[h];

    __shared__ float Qs[8][260];
    __shared__ float Ss[8][128];

    const int t  = threadIdx.x;
    const int ty = t >> 4;
    const int tx = t & 15;
    const int m0 = ty * 8, e0 = tx * 8;

    const int lm  = t >> 1;
    const int ld4 = (t & 1) * 4;
    const float qd = expf(-s * (float)(lm + 1));
    const int sd  = t >> 5;
    const int se4 = (t & 31) * 4;

    const float* qbase = g_qkv + (size_t)(b * BLK) * QKVW + h * 384;
    const float* st    = g_kvst + (size_t)(h * NB + b) * HD * HD;

    float acc[8][8];
#pragma unroll
    for (int i = 0; i < 8; ++i)
#pragma unroll
        for (int j = 0; j < 8; ++j) acc[i][j] = 0.0f;

    for (int dc = 0; dc < 16; ++dc) {
        const int d0 = dc * 8;
        float4 q4 = *(const float4*)(qbase + (size_t)lm * QKVW + d0 + ld4);
        float4 s4 = make_float4(0.f, 0.f, 0.f, 0.f);
        if (t < 256) s4 = *(const float4*)(st + (size_t)(d0 + sd) * HD + se4);
        __syncthreads();
        Qs[ld4 + 0][lm] = q4.x * qd; Qs[ld4 + 1][lm] = q4.y * qd;
        Qs[ld4 + 2][lm] = q4.z * qd; Qs[ld4 + 3][lm] = q4.w * qd;
        if (t < 256) *(float4*)&Ss[sd][se4] = s4;
        __syncthreads();
#pragma unroll
        for (int kk = 0; kk < 8; ++kk) {
            float4 a0 = *(const float4*)&Qs[kk][m0];
            float4 a1 = *(const float4*)&Qs[kk][m0 + 4];
            float4 b0 = *(const float4*)&Ss[kk][e0];
            float4 b1 = *(const float4*)&Ss[kk][e0 + 4];
            float av[8] = {a0.x, a0.y, a0.z, a0.w, a1.x, a1.y, a1.z, a1.w};
            float bv[8] = {b0.x, b0.y, b0.z, b0.w, b1.x, b1.y, b1.z, b1.w};
#pragma unroll
            for (int i = 0; i < 8; ++i)
#pragma unroll
                for (int j = 0; j < 8; ++j) acc[i][j] += av[i] * bv[j];
        }
    }

    float* hbase = g_hidden + (size_t)(b * BLK) * INNER + h * HD;
#pragma unroll
    for (int i = 0; i < 8; ++i) {
        float* Hp = hbase + (size_t)(m0 + i) * INNER + e0;
        *(float4*)Hp       = make_float4(acc[i][0], acc[i][1], acc[i][2], acc[i][3]);
        *(float4*)(Hp + 4) = make_float4(acc[i][4], acc[i][5], acc[i][6], acc[i][7]);
    }
}

// ---------------- attention stage C2 ----------------
__global__ __launch_bounds__(256)
void attn_ointra(const float* __restrict__ slope)
{
    const int mt = blockIdx.x;
    const int b  = blockIdx.y;
    const int h  = blockIdx.z;
    const float s = slope[h];

    __shared__ float Qs[32][132];
    __shared__ float KVs[32][132];
    __shared__ float Ps[32][36];

    const int t = threadIdx.x;
    const float* qbase = g_qkv + (size_t)(b * BLK) * QKVW + h * 384;

#pragma unroll
    for (int r = 0; r < 4; ++r) {
        int idx = t + r * 256;
        int mm = idx >> 5, d4 = (idx & 31) * 4;
        float4 q4 = *(const float4*)(qbase + (size_t)(mt * 32 + mm) * QKVW + d4);
        *(float4*)&Qs[mm][d4] = q4;
    }

    const int p_ty = t >> 4, p_tx = t & 15;
    const int pm0  = p_ty * 2;
    const int om0  = p_ty * 2;
    const int e0   = p_tx * 8;

    float oacc[2][8];
#pragma unroll
    for (int i = 0; i < 2; ++i)
#pragma unroll
        for (int j = 0; j < 8; ++j) oacc[i][j] = 0.0f;

    for (int nt = 0; nt <= mt; ++nt) {
        __syncthreads();
#pragma unroll
        for (int r = 0; r < 4; ++r) {
            int idx = t + r * 256;
            int nn = idx >> 5, d4 = (idx & 31) * 4;
            float4 k4 = *(const float4*)(qbase + 128 + (size_t)(nt * 32 + nn) * QKVW + d4);
            *(float4*)&KVs[nn][d4] = k4;
        }
        __syncthreads();

        float p00 = 0.f, p01 = 0.f, p10 = 0.f, p11 = 0.f;
#pragma unroll 4
        for (int d = 0; d < 128; ++d) {
            float a0 = Qs[pm0][d], a1 = Qs[pm0 + 1][d];
            float b0 = KVs[p_tx][d], b1 = KVs[p_tx + 16][d];
            p00 += a0 * b0; p01 += a0 * b1;
            p10 += a1 * b0; p11 += a1 * b1;
        }
        const int mg0 = mt * 32 + pm0, mg1 = mg0 + 1;
        const int ng0 = nt * 32 + p_tx, ng1 = nt * 32 + p_tx + 16;
        Ps[pm0][p_tx]          = (mg0 >= ng0) ? p00 * expf(-s * (float)(mg0 - ng0)) : 0.0f;
        Ps[pm0][p_tx + 16]     = (mg0 >= ng1) ? p01 * expf(-s * (float)(mg0 - ng1)) : 0.0f;
        Ps[pm0 + 1][p_tx]      = (mg1 >= ng0) ? p10 * expf(-s * (float)(mg1 - ng0)) : 0.0f;
        Ps[pm0 + 1][p_tx + 16] = (mg1 >= ng1) ? p11 * expf(-s * (float)(mg1 - ng1)) : 0.0f;
        __syncthreads();

#pragma unroll
        for (int r = 0; r < 4; ++r) {
            int idx = t + r * 256;
            int nn = idx >> 5, d4 = (idx & 31) * 4;
            float4 v4 = *(const float4*)(qbase + 256 + (size_t)(nt * 32 + nn) * QKVW + d4);
            *(float4*)&KVs[nn][d4] = v4;
        }
        __syncthreads();

#pragma unroll 4
        for (int n = 0; n < 32; ++n) {
            float a0 = Ps[om0][n], a1 = Ps[om0 + 1][n];
            float4 v0 = *(const float4*)&KVs[n][e0];
            float4 v1 = *(const float4*)&KVs[n][e0 + 4];
            oacc[0][0] += a0 * v0.x; oacc[0][1] += a0 * v0.y;
            oacc[0][2] += a0 * v0.z; oacc[0][3] += a0 * v0.w;
            oacc[0][4] += a0 * v1.x; oacc[0][5] += a0 * v1.y;
            oacc[0][6] += a0 * v1.z; oacc[0][7] += a0 * v1.w;
            oacc[1][0] += a1 * v0.x; oacc[1][1] += a1 * v0.y;
            oacc[1][2] += a1 * v0.z; oacc[1][3] += a1 * v0.w;
            oacc[1][4] += a1 * v1.x; oacc[1][5] += a1 * v1.y;
            oacc[1][6] += a1 * v1.z; oacc[1][7] += a1 * v1.w;
        }
    }

    float* hbase = g_hidden + (size_t)(b * BLK + mt * 32) * INNER + h * HD;
#pragma unroll
    for (int i = 0; i < 2; ++i) {
        float* Hp = hbase + (size_t)(om0 + i) * INNER + e0;
        float4 o0 = *(float4*)Hp;
        float4 o1 = *(float4*)(Hp + 4);
        o0.x += oacc[i][0]; o0.y += oacc[i][1]; o0.z += oacc[i][2]; o0.w += oacc[i][3];
        o1.x += oacc[i][4]; o1.y += oacc[i][5]; o1.z += oacc[i][6]; o1.w += oacc[i][7];
        *(float4*)Hp       = o0;
        *(float4*)(Hp + 4) = o1;
    }
}

// ---------------- RMSNorm * weight * gate -> fp16 (for GEMM3) ----------------
__global__ __launch_bounds__(256)
void rmsnorm_gate(const float* __restrict__ nw)
{
    const int m = blockIdx.x;
    const int t = threadIdx.x;
    const float* hrow = g_hidden + (size_t)m * INNER;
    const float* grow = g_gate + (size_t)m * INNER;
    __half* orow = g_ghalf + (size_t)m * INNER;

    float ss = 0.0f;
    for (int i = t; i < INNER / 4; i += 256) {
        float4 h4 = *(const float4*)(hrow + i * 4);
        ss += h4.x * h4.x + h4.y * h4.y + h4.z * h4.z + h4.w * h4.w;
    }
    __shared__ float red[256];
    red[t] = ss;
    __syncthreads();
    for (int s2 = 128; s2 > 0; s2 >>= 1) {
        if (t < s2) red[t] += red[t + s2];
        __syncthreads();
    }
    const float rs = rsqrtf(red[0] / (float)INNER + EPS_RMS);

    for (int i = t; i < INNER / 4; i += 256) {
        float4 h4 = *(const float4*)(hrow + i * 4);
        float4 g4 = *(const float4*)(grow + i * 4);
        float4 w4 = *(const float4*)(nw + i * 4);
        __half2 o0 = __floats2half2_rn(g4.x * (h4.x * rs * w4.x),
                                       g4.y * (h4.y * rs * w4.y));
        __half2 o1 = __floats2half2_rn(g4.z * (h4.z * rs * w4.z),
                                       g4.w * (h4.w * rs * w4.w));
        uint2 o;
        o.x = *(uint32_t*)&o0; o.y = *(uint32_t*)&o1;
        *(uint2*)(orow + i * 4) = o;
    }
}

// ---------------- launcher ----------------
extern "C" void kernel_launch(void* const* d_in, const int* in_sizes, int n_in,
                              void* d_out, int out_size)
{
    (void)in_sizes; (void)n_in; (void)out_size;
    const float* x     = (const float*)d_in[0];
    const float* wqkv  = (const float*)d_in[1];
    const float* wgate = (const float*)d_in[2];
    const float* wout  = (const float*)d_in[3];
    const float* nw    = (const float*)d_in[4];
    const float* kvc   = (const float*)d_in[5];
    const float* slope = (const float*)d_in[6];
    float* out = (float*)d_out;

    float *p_qkv = nullptr, *p_gate = nullptr;
    __half *p_xh = nullptr, *p_wqkvh = nullptr, *p_wgateh = nullptr,
           *p_wouth = nullptr, *p_ghalf = nullptr;
    cudaGetSymbolAddress((void**)&p_qkv, g_qkv);
    cudaGetSymbolAddress((void**)&p_gate, g_gate);
    cudaGetSymbolAddress((void**)&p_xh, g_xh);
    cudaGetSymbolAddress((void**)&p_wqkvh, g_wqkvh);
    cudaGetSymbolAddress((void**)&p_wgateh, g_wgateh);
    cudaGetSymbolAddress((void**)&p_wouth, g_wouth);
    cudaGetSymbolAddress((void**)&p_ghalf, g_ghalf);

    cudaFuncSetAttribute(gemm_mma<EPI_SILU>, cudaFuncAttributeMaxDynamicSharedMemorySize, GEMM_SMEM);
    cudaFuncSetAttribute(gemm_mma<EPI_SIGM>, cudaFuncAttributeMaxDynamicSharedMemorySize, GEMM_SMEM);
    cudaFuncSetAttribute(gemm_mma<EPI_NONE>, cudaFuncAttributeMaxDynamicSharedMemorySize, GEMM_SMEM);

    // fp32 -> fp16 conversions
    cvt_f16_kernel<<<(SEQ * HDIM / 8 + 255) / 256, 256>>>(x, p_xh, SEQ * HDIM / 8);
    cvt_f16_kernel<<<(QKVW * HDIM / 8 + 255) / 256, 256>>>(wqkv, p_wqkvh, QKVW * HDIM / 8);
    cvt_f16_kernel<<<(INNER * HDIM / 8 + 255) / 256, 256>>>(wgate, p_wgateh, INNER * HDIM / 8);
    cvt_f16_kernel<<<(HDIM * INNER / 8 + 255) / 256, 256>>>(wout, p_wouth, HDIM * INNER / 8);

    // qkv = silu(x @ w_qkv^T)
    gemm_mma<EPI_SILU><<<dim3(QKVW / BN, SEQ / BM), NTHR, GEMM_SMEM>>>(p_xh, p_wqkvh, p_qkv, QKVW);
    // gate = sigmoid(x @ w_gate^T)
    gemm_mma<EPI_SIGM><<<dim3(INNER / BN, SEQ / BM), NTHR, GEMM_SMEM>>>(p_xh, p_wgateh, p_gate, INNER);

    // lightning attention (fp32)
    attn_kvblocks<<<dim3(NB, NH), 256>>>(slope);
    attn_scan<<<(NH * HD * HD) / 256, 256>>>(kvc, slope);
    attn_ointer<<<dim3(NB, NH), 512>>>(slope);
    attn_ointra<<<dim3(8, NB, NH), 256>>>(slope);

    // rmsnorm * weight * gate -> fp16
    rmsnorm_gate<<<SEQ, 256>>>(nw);

    // out = (gate * normed) @ w_out^T
    gemm_mma<EPI_NONE><<<dim3(HDIM / BN, SEQ / BM), NTHR, GEMM_SMEM>>>(p_ghalf, p_wouth, out, HDIM);
}

// round 8
// speedup vs baseline: 1.1140x; 1.1140x over previous
#include <cuda_runtime.h>
#include <cuda_fp16.h>
#include <math.h>
#include <stdint.h>

#define SEQ   4096
#define HDIM  4096
#define INNER 4096
#define NH    32
#define HD    128
#define BLK   256
#define NB    16
#define QKVW  12288
#define EPS_RMS 1e-5f

#define GK    4096
#define BM    128
#define BN    128
#define BK    64
#define NTHR  128
#define KTILES (GK / BK)    // 64
#define KPADH 72
#define STGH_A (128 * KPADH)
#define STAGE_BYTES (2 * STGH_A * 2)    // 36864
#define NSTG  3
#define GEMM_SMEM (NSTG * STAGE_BYTES)  // 110592 -> 2 CTAs/SM

#define KP2   136                        // attention smem row: 128 + 8 pad halfs
#define OINTER_SMEM ((256 + 128) * KP2 * 2)   // 104448 bytes

// ---------------- scratch ----------------
__device__ float  g_qkv[(size_t)SEQ * QKVW];      // fp32 qkv (for ointra)
__device__ __half g_qkvh[(size_t)SEQ * QKVW];     // fp16 qkv (for mma attention)
__device__ float  g_hidden[(size_t)SEQ * INNER];
__device__ float  g_gate[(size_t)SEQ * INNER];
__device__ float  g_S[(size_t)NH * NB * HD * HD];
__device__ float  g_kvst[(size_t)NH * NB * HD * HD];
__device__ __half g_xh[(size_t)SEQ * HDIM];
__device__ __half g_wqkvh[(size_t)QKVW * HDIM];
__device__ __half g_wgateh[(size_t)INNER * HDIM];
__device__ __half g_wouth[(size_t)HDIM * INNER];
__device__ __half g_ghalf[(size_t)SEQ * INNER];

// ---------------- helpers ----------------
__device__ __forceinline__ uint32_t smem_u32(const void* p) {
    uint32_t a;
    asm("{ .reg .u64 t; cvta.to.shared.u64 t, %1; cvt.u32.u64 %0, t; }" : "=r"(a) : "l"(p));
    return a;
}

__device__ __forceinline__ void cp_async16(uint32_t dst, const void* src) {
    asm volatile("cp.async.cg.shared.global [%0], [%1], 16;" :: "r"(dst), "l"(src));
}
#define CP_COMMIT() asm volatile("cp.async.commit_group;" ::: "memory")
#define CP_WAIT(n)  asm volatile("cp.async.wait_group %0;" :: "n"(n) : "memory")

__device__ __forceinline__ void ldsm_x4(uint32_t& r0, uint32_t& r1, uint32_t& r2, uint32_t& r3,
                                        uint32_t addr) {
    asm volatile("ldmatrix.sync.aligned.m8n8.x4.shared.b16 {%0,%1,%2,%3}, [%4];"
        : "=r"(r0), "=r"(r1), "=r"(r2), "=r"(r3) : "r"(addr));
}
__device__ __forceinline__ void ldsm_x4_t(uint32_t& r0, uint32_t& r1, uint32_t& r2, uint32_t& r3,
                                          uint32_t addr) {
    asm volatile("ldmatrix.sync.aligned.m8n8.x4.trans.shared.b16 {%0,%1,%2,%3}, [%4];"
        : "=r"(r0), "=r"(r1), "=r"(r2), "=r"(r3) : "r"(addr));
}

__device__ __forceinline__ void mma_f16(float* c, const uint32_t* a, const uint32_t* b) {
    asm volatile(
        "mma.sync.aligned.m16n8k16.row.col.f32.f16.f16.f32 "
        "{%0,%1,%2,%3}, {%4,%5,%6,%7}, {%8,%9}, {%0,%1,%2,%3};"
        : "+f"(c[0]), "+f"(c[1]), "+f"(c[2]), "+f"(c[3])
        : "r"(a[0]), "r"(a[1]), "r"(a[2]), "r"(a[3]), "r"(b[0]), "r"(b[1]));
}

#define EPI_NONE 0
#define EPI_SILU 1
#define EPI_SIGM 2
template <int EPI>
__device__ __forceinline__ float epi(float v) {
    if (EPI == EPI_SILU) return v / (1.0f + expf(-v));
    if (EPI == EPI_SIGM) return 1.0f / (1.0f + expf(-v));
    return v;
}

// fp32 -> fp16 conversion kernel
__global__ __launch_bounds__(256)
void cvt_f16_kernel(const float* __restrict__ in, __half* __restrict__ out, int n8) {
    int i = blockIdx.x * 256 + threadIdx.x;
    if (i < n8) {
        float4 v0 = ((const float4*)in)[i * 2];
        float4 v1 = ((const float4*)in)[i * 2 + 1];
        __half2 h0 = __floats2half2_rn(v0.x, v0.y);
        __half2 h1 = __floats2half2_rn(v0.z, v0.w);
        __half2 h2 = __floats2half2_rn(v1.x, v1.y);
        __half2 h3 = __floats2half2_rn(v1.z, v1.w);
        uint4 o;
        o.x = *(uint32_t*)&h0; o.y = *(uint32_t*)&h1;
        o.z = *(uint32_t*)&h2; o.w = *(uint32_t*)&h3;
        ((uint4*)out)[i] = o;
    }
}

// ---------------- fp16 mma.sync GEMM (round-6 proven body) ----------------
__device__ __forceinline__ void g_load_stage(uint32_t sbase, int slot, int s,
                                             const __half* __restrict__ Ab,
                                             const __half* __restrict__ Bb, int t)
{
    const uint32_t stA = sbase + slot * STAGE_BYTES;
    const uint32_t stB = stA + STGH_A * 2;
    const __half* ga = Ab + (size_t)s * BK;
    const __half* gb = Bb + (size_t)s * BK;
#pragma unroll
    for (int i = 0; i < 8; ++i) {
        int id = t + NTHR * i;
        int row = id >> 3, c = id & 7;
        cp_async16(stA + (row * KPADH + c * 8) * 2, ga + (size_t)row * GK + c * 8);
    }
#pragma unroll
    for (int i = 0; i < 8; ++i) {
        int id = t + NTHR * i;
        int row = id >> 3, c = id & 7;
        cp_async16(stB + (row * KPADH + c * 8) * 2, gb + (size_t)row * GK + c * 8);
    }
}

template <int EPI, bool WH>
__global__ __launch_bounds__(NTHR, 2)
void gemm_mma(const __half* __restrict__ A, const __half* __restrict__ B,
              float* __restrict__ C, __half* __restrict__ Ch, int Ntot)
{
    extern __shared__ __align__(128) __half smem[];
    const uint32_t sbase = smem_u32(smem);
    const int t    = threadIdx.x;
    const int wid  = t >> 5;
    const int lane = t & 31;
    const int bm = blockIdx.y * BM;
    const int bn = blockIdx.x * BN;
    const __half* Ab = A + (size_t)bm * GK;
    const __half* Bb = B + (size_t)bn * GK;

    const int wm = (wid & 1) * 64;
    const int wn = (wid >> 1) * 64;
    const int r  = lane >> 2;
    const int q  = lane & 3;

    float c[4][8][4];
#pragma unroll
    for (int i = 0; i < 4; ++i)
#pragma unroll
        for (int j = 0; j < 8; ++j)
#pragma unroll
            for (int p = 0; p < 4; ++p) c[i][j][p] = 0.0f;

    g_load_stage(sbase, 0, 0, Ab, Bb, t); CP_COMMIT();
    g_load_stage(sbase, 1, 1, Ab, Bb, t); CP_COMMIT();

    for (int s = 0; s < KTILES; ++s) {
        const int slot = s % NSTG;
        CP_WAIT(1);
        __syncthreads();

        if (s + 2 < KTILES) {
            g_load_stage(sbase, (s + 2) % NSTG, s + 2, Ab, Bb, t);
        }
        CP_COMMIT();

        const __half* As = smem + slot * (STAGE_BYTES / 2);
        const __half* Bs = As + STGH_A;

#pragma unroll
        for (int ks = 0; ks < 4; ++ks) {
            const int k0 = ks * 16;
            uint32_t af[4][4], bf[8][2];
#pragma unroll
            for (int i = 0; i < 4; ++i) {
                const __half* ap = As + (wm + i * 16 + r) * KPADH + k0 + 2 * q;
                af[i][0] = *(const uint32_t*)(ap);
                af[i][1] = *(const uint32_t*)(ap + 8 * KPADH);
                af[i][2] = *(const uint32_t*)(ap + 8);
                af[i][3] = *(const uint32_t*)(ap + 8 * KPADH + 8);
            }
#pragma unroll
            for (int j = 0; j < 8; ++j) {
                const __half* bp = Bs + (wn + j * 8 + r) * KPADH + k0 + 2 * q;
                bf[j][0] = *(const uint32_t*)(bp);
                bf[j][1] = *(const uint32_t*)(bp + 8);
            }
#pragma unroll
            for (int i = 0; i < 4; ++i)
#pragma unroll
                for (int j = 0; j < 8; ++j)
                    mma_f16(c[i][j], af[i], bf[j]);
        }
    }

#pragma unroll
    for (int i = 0; i < 4; ++i) {
        const int row0 = bm + wm + i * 16 + r;
#pragma unroll
        for (int j = 0; j < 8; ++j) {
            const int col = bn + wn + j * 8 + 2 * q;
            float2 v0 = make_float2(epi<EPI>(c[i][j][0]), epi<EPI>(c[i][j][1]));
            float2 v1 = make_float2(epi<EPI>(c[i][j][2]), epi<EPI>(c[i][j][3]));
            *(float2*)(C + (size_t)row0 * Ntot + col)       = v0;
            *(float2*)(C + (size_t)(row0 + 8) * Ntot + col) = v1;
            if (WH) {
                __half2 h0 = __floats2half2_rn(v0.x, v0.y);
                __half2 h1 = __floats2half2_rn(v1.x, v1.y);
                *(__half2*)(Ch + (size_t)row0 * Ntot + col)       = h0;
                *(__half2*)(Ch + (size_t)(row0 + 8) * Ntot + col) = h1;
            }
        }
    }
}

// ---------------- attention stage A (fp16 mma): S[d][e] = sum_i k'[i,d] v[i,e] ----------------
__global__ __launch_bounds__(128)
void attn_kvblocks_mma(const float* __restrict__ slope)
{
    const int b = blockIdx.x;
    const int h = blockIdx.y;
    const float s = slope[h];

    __shared__ __half Ks[64][KP2];
    __shared__ __half Vs[64][KP2];

    const int t = threadIdx.x;
    const int w = t >> 5, lane = t & 31;
    const int wm = w * 32;                        // warp d-range base
    const int r = lane >> 2, q = lane & 3;
    const int trow = (lane & 7) + ((lane >> 4) & 1) * 8;
    const int tcol = ((lane >> 3) & 1) * 8;

    const __half* kbase = g_qkvh + (size_t)(b * BLK) * QKVW + h * 384 + 128;
    const __half* vbase = kbase + 128;

    const uint32_t sK = smem_u32(Ks);
    const uint32_t sV = smem_u32(Vs);

    float c[2][16][4];
#pragma unroll
    for (int i = 0; i < 2; ++i)
#pragma unroll
        for (int j = 0; j < 16; ++j)
#pragma unroll
            for (int p = 0; p < 4; ++p) c[i][j][p] = 0.0f;

    for (int ch = 0; ch < 4; ++ch) {
        __syncthreads();
#pragma unroll
        for (int it = 0; it < 8; ++it) {
            int id = t + 128 * it;                // 0..1023
            int row = id >> 4;                    // 0..63
            int c16 = id & 15;                    // which 8-half chunk
            int i = ch * 64 + row;
            float kd = expf(-s * (float)(255 - i));
            uint4 k4 = *(const uint4*)(kbase + (size_t)i * QKVW + c16 * 8);
            __half2* hp = (__half2*)&k4;
#pragma unroll
            for (int z = 0; z < 4; ++z) {
                float2 f = __half22float2(hp[z]);
                hp[z] = __floats2half2_rn(f.x * kd, f.y * kd);
            }
            *(uint4*)&Ks[row][c16 * 8] = k4;
            uint4 v4 = *(const uint4*)(vbase + (size_t)i * QKVW + c16 * 8);
            *(uint4*)&Vs[row][c16 * 8] = v4;
        }
        __syncthreads();

#pragma unroll
        for (int kc = 0; kc < 4; ++kc) {
            uint32_t af[2][4], bf[16][2];
#pragma unroll
            for (int i16 = 0; i16 < 2; ++i16) {
                uint32_t addr = sK + ((kc * 16 + trow) * KP2 + wm + i16 * 16 + tcol) * 2;
                ldsm_x4_t(af[i16][0], af[i16][1], af[i16][2], af[i16][3], addr);
            }
#pragma unroll
            for (int jj = 0; jj < 8; ++jj) {
                uint32_t addr = sV + ((kc * 16 + trow) * KP2 + jj * 16 + tcol) * 2;
                ldsm_x4_t(bf[2 * jj][0], bf[2 * jj + 1][0], bf[2 * jj][1], bf[2 * jj + 1][1], addr);
            }
#pragma unroll
            for (int i16 = 0; i16 < 2; ++i16)
#pragma unroll
                for (int j = 0; j < 16; ++j)
                    mma_f16(c[i16][j], af[i16], bf[j]);
        }
    }

    float* Sp = g_S + (size_t)(h * NB + b) * HD * HD;
#pragma unroll
    for (int i16 = 0; i16 < 2; ++i16) {
        const int d0 = wm + i16 * 16 + r;
#pragma unroll
        for (int j = 0; j < 16; ++j) {
            const int e = j * 8 + 2 * q;
            *(float2*)(Sp + (size_t)d0 * HD + e)       = make_float2(c[i16][j][0], c[i16][j][1]);
            *(float2*)(Sp + (size_t)(d0 + 8) * HD + e) = make_float2(c[i16][j][2], c[i16][j][3]);
        }
    }
}

// ---------------- attention stage B (unchanged fp32 scan) ----------------
__global__ void attn_scan(const float* __restrict__ kv_cache, const float* __restrict__ slope)
{
    const int g = blockIdx.x * 256 + threadIdx.x;
    const int h = g >> 14;
    const int e = g & 16383;
    const float dec = expf(-slope[h] * 256.0f);
    float c = kv_cache[(size_t)h * 16384 + e];
    const size_t base = (size_t)h * NB * 16384 + e;
#pragma unroll
    for (int b = 0; b < NB; ++b) {
        g_kvst[base + (size_t)b * 16384] = c;
        c = dec * c + g_S[base + (size_t)b * 16384];
    }
}

// ---------------- attention stage C1 (fp16 mma): O = qdec .* (q @ kvst) ----------------
__global__ __launch_bounds__(256, 1)
void attn_ointer_mma(const float* __restrict__ slope)
{
    extern __shared__ __align__(128) __half asm_sm[];
    __half (*Qs)[KP2]  = (__half(*)[KP2])asm_sm;
    __half (*KVs)[KP2] = (__half(*)[KP2])(asm_sm + 256 * KP2);

    const int b = blockIdx.x;
    const int h = blockIdx.y;
    const float s = slope[h];

    const int t = threadIdx.x;
    const int w = t >> 5, lane = t & 31;          // 8 warps
    const int wm = w * 32;                        // warp m-range base (of 256)
    const int r = lane >> 2, q = lane & 3;
    const int lrow = (lane & 7) + ((lane >> 3) & 1) * 8;
    const int lcol = (lane >> 4) * 8;
    const int trow = (lane & 7) + ((lane >> 4) & 1) * 8;
    const int tcol = ((lane >> 3) & 1) * 8;

    const __half* qbase = g_qkvh + (size_t)(b * BLK) * QKVW + h * 384;
    const float*  st    = g_kvst + (size_t)(h * NB + b) * HD * HD;

    // stage q (fp16): 256 rows x 16 uint4
#pragma unroll
    for (int it = 0; it < 16; ++it) {
        int id = t + 256 * it;                    // 0..4095
        int row = id >> 4, c16 = id & 15;
        uint4 v = *(const uint4*)(qbase + (size_t)row * QKVW + c16 * 8);
        *(uint4*)&Qs[row][c16 * 8] = v;
    }
    // stage kvst -> fp16: 128 rows x 32 float4
#pragma unroll
    for (int it = 0; it < 16; ++it) {
        int id = t + 256 * it;                    // 0..4095
        int row = id >> 5, c4 = id & 31;
        float4 f = *(const float4*)(st + (size_t)row * HD + c4 * 4);
        __half2 h0 = __floats2half2_rn(f.x, f.y);
        __half2 h1 = __floats2half2_rn(f.z, f.w);
        uint2 o; o.x = *(uint32_t*)&h0; o.y = *(uint32_t*)&h1;
        *(uint2*)&KVs[row][c4 * 4] = o;
    }
    __syncthreads();

    const uint32_t sQ  = smem_u32(Qs);
    const uint32_t sKV = smem_u32(KVs);

    float c[2][16][4];
#pragma unroll
    for (int i = 0; i < 2; ++i)
#pragma unroll
        for (int j = 0; j < 16; ++j)
#pragma unroll
            for (int p = 0; p < 4; ++p) c[i][j][p] = 0.0f;

#pragma unroll
    for (int kc = 0; kc < 8; ++kc) {
        uint32_t af[2][4], bf[16][2];
#pragma unroll
        for (int i16 = 0; i16 < 2; ++i16) {
            uint32_t addr = sQ + ((wm + i16 * 16 + lrow) * KP2 + kc * 16 + lcol) * 2;
            ldsm_x4(af[i16][0], af[i16][1], af[i16][2], af[i16][3], addr);
        }
#pragma unroll
        for (int jj = 0; jj < 8; ++jj) {
            uint32_t addr = sKV + ((kc * 16 + trow) * KP2 + jj * 16 + tcol) * 2;
            ldsm_x4_t(bf[2 * jj][0], bf[2 * jj + 1][0], bf[2 * jj][1], bf[2 * jj + 1][1], addr);
        }
#pragma unroll
        for (int i16 = 0; i16 < 2; ++i16)
#pragma unroll
            for (int j = 0; j < 16; ++j)
                mma_f16(c[i16][j], af[i16], bf[j]);
    }

    float* hbase = g_hidden + (size_t)(b * BLK) * INNER + h * HD;
#pragma unroll
    for (int i16 = 0; i16 < 2; ++i16) {
        const int m0 = wm + i16 * 16 + r;
        const float qd0 = expf(-s * (float)(m0 + 1));
        const float qd8 = expf(-s * (float)(m0 + 9));
#pragma unroll
        for (int j = 0; j < 16; ++j) {
            const int e = j * 8 + 2 * q;
            *(float2*)(hbase + (size_t)m0 * INNER + e) =
                make_float2(c[i16][j][0] * qd0, c[i16][j][1] * qd0);
            *(float2*)(hbase + (size_t)(m0 + 8) * INNER + e) =
                make_float2(c[i16][j][2] * qd8, c[i16][j][3] * qd8);
        }
    }
}

// ---------------- attention stage C2 (unchanged fp32) ----------------
__global__ __launch_bounds__(256)
void attn_ointra(const float* __restrict__ slope)
{
    const int mt = blockIdx.x;
    const int b  = blockIdx.y;
    const int h  = blockIdx.z;
    const float s = slope[h];

    __shared__ float Qs[32][132];
    __shared__ float KVs[32][132];
    __shared__ float Ps[32][36];

    const int t = threadIdx.x;
    const float* qbase = g_qkv + (size_t)(b * BLK) * QKVW + h * 384;

#pragma unroll
    for (int r = 0; r < 4; ++r) {
        int idx = t + r * 256;
        int mm = idx >> 5, d4 = (idx & 31) * 4;
        float4 q4 = *(const float4*)(qbase + (size_t)(mt * 32 + mm) * QKVW + d4);
        *(float4*)&Qs[mm][d4] = q4;
    }

    const int p_ty = t >> 4, p_tx = t & 15;
    const int pm0  = p_ty * 2;
    const int om0  = p_ty * 2;
    const int e0   = p_tx * 8;

    float oacc[2][8];
#pragma unroll
    for (int i = 0; i < 2; ++i)
#pragma unroll
        for (int j = 0; j < 8; ++j) oacc[i][j] = 0.0f;

    for (int nt = 0; nt <= mt; ++nt) {
        __syncthreads();
#pragma unroll
        for (int r = 0; r < 4; ++r) {
            int idx = t + r * 256;
            int nn = idx >> 5, d4 = (idx & 31) * 4;
            float4 k4 = *(const float4*)(qbase + 128 + (size_t)(nt * 32 + nn) * QKVW + d4);
            *(float4*)&KVs[nn][d4] = k4;
        }
        __syncthreads();

        float p00 = 0.f, p01 = 0.f, p10 = 0.f, p11 = 0.f;
#pragma unroll 4
        for (int d = 0; d < 128; ++d) {
            float a0 = Qs[pm0][d], a1 = Qs[pm0 + 1][d];
            float b0 = KVs[p_tx][d], b1 = KVs[p_tx + 16][d];
            p00 += a0 * b0; p01 += a0 * b1;
            p10 += a1 * b0; p11 += a1 * b1;
        }
        const int mg0 = mt * 32 + pm0, mg1 = mg0 + 1;
        const int ng0 = nt * 32 + p_tx, ng1 = nt * 32 + p_tx + 16;
        Ps[pm0][p_tx]          = (mg0 >= ng0) ? p00 * expf(-s * (float)(mg0 - ng0)) : 0.0f;
        Ps[pm0][p_tx + 16]     = (mg0 >= ng1) ? p01 * expf(-s * (float)(mg0 - ng1)) : 0.0f;
        Ps[pm0 + 1][p_tx]      = (mg1 >= ng0) ? p10 * expf(-s * (float)(mg1 - ng0)) : 0.0f;
        Ps[pm0 + 1][p_tx + 16] = (mg1 >= ng1) ? p11 * expf(-s * (float)(mg1 - ng1)) : 0.0f;
        __syncthreads();

#pragma unroll
        for (int r = 0; r < 4; ++r) {
            int idx = t + r * 256;
            int nn = idx >> 5, d4 = (idx & 31) * 4;
            float4 v4 = *(const float4*)(qbase + 256 + (size_t)(nt * 32 + nn) * QKVW + d4);
            *(float4*)&KVs[nn][d4] = v4;
        }
        __syncthreads();

#pragma unroll 4
        for (int n = 0; n < 32; ++n) {
            float a0 = Ps[om0][n], a1 = Ps[om0 + 1][n];
            float4 v0 = *(const float4*)&KVs[n][e0];
            float4 v1 = *(const float4*)&KVs[n][e0 + 4];
            oacc[0][0] += a0 * v0.x; oacc[0][1] += a0 * v0.y;
            oacc[0][2] += a0 * v0.z; oacc[0][3] += a0 * v0.w;
            oacc[0][4] += a0 * v1.x; oacc[0][5] += a0 * v1.y;
            oacc[0][6] += a0 * v1.z; oacc[0][7] += a0 * v1.w;
            oacc[1][0] += a1 * v0.x; oacc[1][1] += a1 * v0.y;
            oacc[1][2] += a1 * v0.z; oacc[1][3] += a1 * v0.w;
            oacc[1][4] += a1 * v1.x; oacc[1][5] += a1 * v1.y;
            oacc[1][6] += a1 * v1.z; oacc[1][7] += a1 * v1.w;
        }
    }

    float* hbase = g_hidden + (size_t)(b * BLK + mt * 32) * INNER + h * HD;
#pragma unroll
    for (int i = 0; i < 2; ++i) {
        float* Hp = hbase + (size_t)(om0 + i) * INNER + e0;
        float4 o0 = *(float4*)Hp;
        float4 o1 = *(float4*)(Hp + 4);
        o0.x += oacc[i][0]; o0.y += oacc[i][1]; o0.z += oacc[i][2]; o0.w += oacc[i][3];
        o1.x += oacc[i][4]; o1.y += oacc[i][5]; o1.z += oacc[i][6]; o1.w += oacc[i][7];
        *(float4*)Hp       = o0;
        *(float4*)(Hp + 4) = o1;
    }
}

// ---------------- RMSNorm * weight * gate -> fp16 ----------------
__global__ __launch_bounds__(256)
void rmsnorm_gate(const float* __restrict__ nw)
{
    const int m = blockIdx.x;
    const int t = threadIdx.x;
    const float* hrow = g_hidden + (size_t)m * INNER;
    const float* grow = g_gate + (size_t)m * INNER;
    __half* orow = g_ghalf + (size_t)m * INNER;

    float ss = 0.0f;
    for (int i = t; i < INNER / 4; i += 256) {
        float4 h4 = *(const float4*)(hrow + i * 4);
        ss += h4.x * h4.x + h4.y * h4.y + h4.z * h4.z + h4.w * h4.w;
    }
    __shared__ float red[256];
    red[t] = ss;
    __syncthreads();
    for (int s2 = 128; s2 > 0; s2 >>= 1) {
        if (t < s2) red[t] += red[t + s2];
        __syncthreads();
    }
    const float rs = rsqrtf(red[0] / (float)INNER + EPS_RMS);

    for (int i = t; i < INNER / 4; i += 256) {
        float4 h4 = *(const float4*)(hrow + i * 4);
        float4 g4 = *(const float4*)(grow + i * 4);
        float4 w4 = *(const float4*)(nw + i * 4);
        __half2 o0 = __floats2half2_rn(g4.x * (h4.x * rs * w4.x),
                                       g4.y * (h4.y * rs * w4.y));
        __half2 o1 = __floats2half2_rn(g4.z * (h4.z * rs * w4.z),
                                       g4.w * (h4.w * rs * w4.w));
        uint2 o;
        o.x = *(uint32_t*)&o0; o.y = *(uint32_t*)&o1;
        *(uint2*)(orow + i * 4) = o;
    }
}

// ---------------- launcher ----------------
extern "C" void kernel_launch(void* const* d_in, const int* in_sizes, int n_in,
                              void* d_out, int out_size)
{
    (void)in_sizes; (void)n_in; (void)out_size;
    const float* x     = (const float*)d_in[0];
    const float* wqkv  = (const float*)d_in[1];
    const float* wgate = (const float*)d_in[2];
    const float* wout  = (const float*)d_in[3];
    const float* nw    = (const float*)d_in[4];
    const float* kvc   = (const float*)d_in[5];
    const float* slope = (const float*)d_in[6];
    float* out = (float*)d_out;

    float *p_qkv = nullptr, *p_gate = nullptr;
    __half *p_qkvh = nullptr, *p_xh = nullptr, *p_wqkvh = nullptr,
           *p_wgateh = nullptr, *p_wouth = nullptr, *p_ghalf = nullptr;
    cudaGetSymbolAddress((void**)&p_qkv, g_qkv);
    cudaGetSymbolAddress((void**)&p_qkvh, g_qkvh);
    cudaGetSymbolAddress((void**)&p_gate, g_gate);
    cudaGetSymbolAddress((void**)&p_xh, g_xh);
    cudaGetSymbolAddress((void**)&p_wqkvh, g_wqkvh);
    cudaGetSymbolAddress((void**)&p_wgateh, g_wgateh);
    cudaGetSymbolAddress((void**)&p_wouth, g_wouth);
    cudaGetSymbolAddress((void**)&p_ghalf, g_ghalf);

    cudaFuncSetAttribute((const void*)gemm_mma<EPI_SILU, true>,  cudaFuncAttributeMaxDynamicSharedMemorySize, GEMM_SMEM);
    cudaFuncSetAttribute((const void*)gemm_mma<EPI_SIGM, false>, cudaFuncAttributeMaxDynamicSharedMemorySize, GEMM_SMEM);
    cudaFuncSetAttribute((const void*)gemm_mma<EPI_NONE, false>, cudaFuncAttributeMaxDynamicSharedMemorySize, GEMM_SMEM);
    cudaFuncSetAttribute((const void*)attn_ointer_mma, cudaFuncAttributeMaxDynamicSharedMemorySize, OINTER_SMEM);

    // fp32 -> fp16 conversions
    cvt_f16_kernel<<<(SEQ * HDIM / 8 + 255) / 256, 256>>>(x, p_xh, SEQ * HDIM / 8);
    cvt_f16_kernel<<<(QKVW * HDIM / 8 + 255) / 256, 256>>>(wqkv, p_wqkvh, QKVW * HDIM / 8);
    cvt_f16_kernel<<<(INNER * HDIM / 8 + 255) / 256, 256>>>(wgate, p_wgateh, INNER * HDIM / 8);
    cvt_f16_kernel<<<(HDIM * INNER / 8 + 255) / 256, 256>>>(wout, p_wouth, HDIM * INNER / 8);

    // qkv = silu(x @ w_qkv^T) -> fp32 (ointra) + fp16 (mma attention)
    gemm_mma<EPI_SILU, true><<<dim3(QKVW / BN, SEQ / BM), NTHR, GEMM_SMEM>>>(p_xh, p_wqkvh, p_qkv, p_qkvh, QKVW);
    // gate = sigmoid(x @ w_gate^T)
    gemm_mma<EPI_SIGM, false><<<dim3(INNER / BN, SEQ / BM), NTHR, GEMM_SMEM>>>(p_xh, p_wgateh, p_gate, nullptr, INNER);

    // lightning attention
    attn_kvblocks_mma<<<dim3(NB, NH), 128>>>(slope);
    attn_scan<<<(NH * HD * HD) / 256, 256>>>(kvc, slope);
    attn_ointer_mma<<<dim3(NB, NH), 256, OINTER_SMEM>>>(slope);
    attn_ointra<<<dim3(8, NB, NH), 256>>>(slope);

    // rmsnorm * weight * gate -> fp16
    rmsnorm_gate<<<SEQ, 256>>>(nw);

    // out = (gate * normed) @ w_out^T
    gemm_mma<EPI_NONE, false><<<dim3(HDIM / BN, SEQ / BM), NTHR, GEMM_SMEM>>>(p_ghalf, p_wouth, out, nullptr, HDIM);
}

// round 9
// speedup vs baseline: 1.3281x; 1.1921x over previous
#include <cuda_runtime.h>
#include <cuda_fp16.h>
#include <math.h>
#include <stdint.h>

#define SEQ   4096
#define HDIM  4096
#define INNER 4096
#define NH    32
#define HD    128
#define BLK   256
#define NB    16
#define QKVW  12288
#define EPS_RMS 1e-5f

#define GK    4096
#define BM    128
#define BN    128
#define BK    64
#define NTHR  128
#define KTILES (GK / BK)    // 64
#define KPADH 72
#define STGH_A (128 * KPADH)
#define STAGE_BYTES (2 * STGH_A * 2)    // 36864
#define NSTG  3
#define GEMM_SMEM (NSTG * STAGE_BYTES)  // 110592 -> 2 CTAs/SM

#define KP2   136                        // attention smem row: 128 + 8 pad halfs
#define OINTER_SMEM ((256 + 128) * KP2 * 2)   // 104448 bytes

#define PSTR  72                         // ointra P-buffer row stride (halfs)
#define OINTRA_SMEM (3 * 256 * KP2 * 2 + 8 * 16 * PSTR * 2)   // 227328 bytes

// ---------------- scratch ----------------
__device__ __half g_qkvh[(size_t)SEQ * QKVW];     // fp16 qkv (all attention)
__device__ float  g_hidden[(size_t)SEQ * INNER];
__device__ float  g_gate[(size_t)SEQ * INNER];
__device__ float  g_S[(size_t)NH * NB * HD * HD];
__device__ float  g_kvst[(size_t)NH * NB * HD * HD];
__device__ __half g_xh[(size_t)SEQ * HDIM];
__device__ __half g_wqkvh[(size_t)QKVW * HDIM];
__device__ __half g_wgateh[(size_t)INNER * HDIM];
__device__ __half g_wouth[(size_t)HDIM * INNER];
__device__ __half g_ghalf[(size_t)SEQ * INNER];

// ---------------- helpers ----------------
__device__ __forceinline__ uint32_t smem_u32(const void* p) {
    uint32_t a;
    asm("{ .reg .u64 t; cvta.to.shared.u64 t, %1; cvt.u32.u64 %0, t; }" : "=r"(a) : "l"(p));
    return a;
}

__device__ __forceinline__ void cp_async16(uint32_t dst, const void* src) {
    asm volatile("cp.async.cg.shared.global [%0], [%1], 16;" :: "r"(dst), "l"(src));
}
#define CP_COMMIT() asm volatile("cp.async.commit_group;" ::: "memory")
#define CP_WAIT(n)  asm volatile("cp.async.wait_group %0;" :: "n"(n) : "memory")

__device__ __forceinline__ void ldsm_x4(uint32_t& r0, uint32_t& r1, uint32_t& r2, uint32_t& r3,
                                        uint32_t addr) {
    asm volatile("ldmatrix.sync.aligned.m8n8.x4.shared.b16 {%0,%1,%2,%3}, [%4];"
        : "=r"(r0), "=r"(r1), "=r"(r2), "=r"(r3) : "r"(addr));
}
__device__ __forceinline__ void ldsm_x4_t(uint32_t& r0, uint32_t& r1, uint32_t& r2, uint32_t& r3,
                                          uint32_t addr) {
    asm volatile("ldmatrix.sync.aligned.m8n8.x4.trans.shared.b16 {%0,%1,%2,%3}, [%4];"
        : "=r"(r0), "=r"(r1), "=r"(r2), "=r"(r3) : "r"(addr));
}

__device__ __forceinline__ void mma_f16(float* c, const uint32_t* a, const uint32_t* b) {
    asm volatile(
        "mma.sync.aligned.m16n8k16.row.col.f32.f16.f16.f32 "
        "{%0,%1,%2,%3}, {%4,%5,%6,%7}, {%8,%9}, {%0,%1,%2,%3};"
        : "+f"(c[0]), "+f"(c[1]), "+f"(c[2]), "+f"(c[3])
        : "r"(a[0]), "r"(a[1]), "r"(a[2]), "r"(a[3]), "r"(b[0]), "r"(b[1]));
}

#define EPI_NONE 0
#define EPI_SILU 1
#define EPI_SIGM 2
template <int EPI>
__device__ __forceinline__ float epi(float v) {
    if (EPI == EPI_SILU) return v / (1.0f + expf(-v));
    if (EPI == EPI_SIGM) return 1.0f / (1.0f + expf(-v));
    return v;
}

// fp32 -> fp16 conversion kernel
__global__ __launch_bounds__(256)
void cvt_f16_kernel(const float* __restrict__ in, __half* __restrict__ out, int n8) {
    int i = blockIdx.x * 256 + threadIdx.x;
    if (i < n8) {
        float4 v0 = ((const float4*)in)[i * 2];
        float4 v1 = ((const float4*)in)[i * 2 + 1];
        __half2 h0 = __floats2half2_rn(v0.x, v0.y);
        __half2 h1 = __floats2half2_rn(v0.z, v0.w);
        __half2 h2 = __floats2half2_rn(v1.x, v1.y);
        __half2 h3 = __floats2half2_rn(v1.z, v1.w);
        uint4 o;
        o.x = *(uint32_t*)&h0; o.y = *(uint32_t*)&h1;
        o.z = *(uint32_t*)&h2; o.w = *(uint32_t*)&h3;
        ((uint4*)out)[i] = o;
    }
}

// ---------------- fp16 mma.sync GEMM (round-6 proven body) ----------------
__device__ __forceinline__ void g_load_stage(uint32_t sbase, int slot, int s,
                                             const __half* __restrict__ Ab,
                                             const __half* __restrict__ Bb, int t)
{
    const uint32_t stA = sbase + slot * STAGE_BYTES;
    const uint32_t stB = stA + STGH_A * 2;
    const __half* ga = Ab + (size_t)s * BK;
    const __half* gb = Bb + (size_t)s * BK;
#pragma unroll
    for (int i = 0; i < 8; ++i) {
        int id = t + NTHR * i;
        int row = id >> 3, c = id & 7;
        cp_async16(stA + (row * KPADH + c * 8) * 2, ga + (size_t)row * GK + c * 8);
    }
#pragma unroll
    for (int i = 0; i < 8; ++i) {
        int id = t + NTHR * i;
        int row = id >> 3, c = id & 7;
        cp_async16(stB + (row * KPADH + c * 8) * 2, gb + (size_t)row * GK + c * 8);
    }
}

template <int EPI, bool WF32, bool WH>
__global__ __launch_bounds__(NTHR, 2)
void gemm_mma(const __half* __restrict__ A, const __half* __restrict__ B,
              float* __restrict__ C, __half* __restrict__ Ch, int Ntot)
{
    extern __shared__ __align__(128) __half smem[];
    const uint32_t sbase = smem_u32(smem);
    const int t    = threadIdx.x;
    const int wid  = t >> 5;
    const int lane = t & 31;
    const int bm = blockIdx.y * BM;
    const int bn = blockIdx.x * BN;
    const __half* Ab = A + (size_t)bm * GK;
    const __half* Bb = B + (size_t)bn * GK;

    const int wm = (wid & 1) * 64;
    const int wn = (wid >> 1) * 64;
    const int r  = lane >> 2;
    const int q  = lane & 3;

    float c[4][8][4];
#pragma unroll
    for (int i = 0; i < 4; ++i)
#pragma unroll
        for (int j = 0; j < 8; ++j)
#pragma unroll
            for (int p = 0; p < 4; ++p) c[i][j][p] = 0.0f;

    g_load_stage(sbase, 0, 0, Ab, Bb, t); CP_COMMIT();
    g_load_stage(sbase, 1, 1, Ab, Bb, t); CP_COMMIT();

    for (int s = 0; s < KTILES; ++s) {
        const int slot = s % NSTG;
        CP_WAIT(1);
        __syncthreads();

        if (s + 2 < KTILES) {
            g_load_stage(sbase, (s + 2) % NSTG, s + 2, Ab, Bb, t);
        }
        CP_COMMIT();

        const __half* As = smem + slot * (STAGE_BYTES / 2);
        const __half* Bs = As + STGH_A;

#pragma unroll
        for (int ks = 0; ks < 4; ++ks) {
            const int k0 = ks * 16;
            uint32_t af[4][4], bf[8][2];
#pragma unroll
            for (int i = 0; i < 4; ++i) {
                const __half* ap = As + (wm + i * 16 + r) * KPADH + k0 + 2 * q;
                af[i][0] = *(const uint32_t*)(ap);
                af[i][1] = *(const uint32_t*)(ap + 8 * KPADH);
                af[i][2] = *(const uint32_t*)(ap + 8);
                af[i][3] = *(const uint32_t*)(ap + 8 * KPADH + 8);
            }
#pragma unroll
            for (int j = 0; j < 8; ++j) {
                const __half* bp = Bs + (wn + j * 8 + r) * KPADH + k0 + 2 * q;
                bf[j][0] = *(const uint32_t*)(bp);
                bf[j][1] = *(const uint32_t*)(bp + 8);
            }
#pragma unroll
            for (int i = 0; i < 4; ++i)
#pragma unroll
                for (int j = 0; j < 8; ++j)
                    mma_f16(c[i][j], af[i], bf[j]);
        }
    }

#pragma unroll
    for (int i = 0; i < 4; ++i) {
        const int row0 = bm + wm + i * 16 + r;
#pragma unroll
        for (int j = 0; j < 8; ++j) {
            const int col = bn + wn + j * 8 + 2 * q;
            float2 v0 = make_float2(epi<EPI>(c[i][j][0]), epi<EPI>(c[i][j][1]));
            float2 v1 = make_float2(epi<EPI>(c[i][j][2]), epi<EPI>(c[i][j][3]));
            if (WF32) {
                *(float2*)(C + (size_t)row0 * Ntot + col)       = v0;
                *(float2*)(C + (size_t)(row0 + 8) * Ntot + col) = v1;
            }
            if (WH) {
                __half2 h0 = __floats2half2_rn(v0.x, v0.y);
                __half2 h1 = __floats2half2_rn(v1.x, v1.y);
                *(__half2*)(Ch + (size_t)row0 * Ntot + col)       = h0;
                *(__half2*)(Ch + (size_t)(row0 + 8) * Ntot + col) = h1;
            }
        }
    }
}

// ---------------- attention stage A (fp16 mma): S[d][e] = sum_i k'[i,d] v[i,e] ----------------
__global__ __launch_bounds__(128)
void attn_kvblocks_mma(const float* __restrict__ slope)
{
    const int b = blockIdx.x;
    const int h = blockIdx.y;
    const float s = slope[h];

    __shared__ __half Ks[64][KP2];
    __shared__ __half Vs[64][KP2];

    const int t = threadIdx.x;
    const int w = t >> 5, lane = t & 31;
    const int wm = w * 32;
    const int r = lane >> 2, q = lane & 3;
    const int trow = (lane & 7) + ((lane >> 4) & 1) * 8;
    const int tcol = ((lane >> 3) & 1) * 8;

    const __half* kbase = g_qkvh + (size_t)(b * BLK) * QKVW + h * 384 + 128;
    const __half* vbase = kbase + 128;

    const uint32_t sK = smem_u32(Ks);
    const uint32_t sV = smem_u32(Vs);

    float c[2][16][4];
#pragma unroll
    for (int i = 0; i < 2; ++i)
#pragma unroll
        for (int j = 0; j < 16; ++j)
#pragma unroll
            for (int p = 0; p < 4; ++p) c[i][j][p] = 0.0f;

    for (int ch = 0; ch < 4; ++ch) {
        __syncthreads();
#pragma unroll
        for (int it = 0; it < 8; ++it) {
            int id = t + 128 * it;
            int row = id >> 4;
            int c16 = id & 15;
            int i = ch * 64 + row;
            float kd = expf(-s * (float)(255 - i));
            uint4 k4 = *(const uint4*)(kbase + (size_t)i * QKVW + c16 * 8);
            __half2* hp = (__half2*)&k4;
#pragma unroll
            for (int z = 0; z < 4; ++z) {
                float2 f = __half22float2(hp[z]);
                hp[z] = __floats2half2_rn(f.x * kd, f.y * kd);
            }
            *(uint4*)&Ks[row][c16 * 8] = k4;
            uint4 v4 = *(const uint4*)(vbase + (size_t)i * QKVW + c16 * 8);
            *(uint4*)&Vs[row][c16 * 8] = v4;
        }
        __syncthreads();

#pragma unroll
        for (int kc = 0; kc < 4; ++kc) {
            uint32_t af[2][4], bf[16][2];
#pragma unroll
            for (int i16 = 0; i16 < 2; ++i16) {
                uint32_t addr = sK + ((kc * 16 + trow) * KP2 + wm + i16 * 16 + tcol) * 2;
                ldsm_x4_t(af[i16][0], af[i16][1], af[i16][2], af[i16][3], addr);
            }
#pragma unroll
            for (int jj = 0; jj < 8; ++jj) {
                uint32_t addr = sV + ((kc * 16 + trow) * KP2 + jj * 16 + tcol) * 2;
                ldsm_x4_t(bf[2 * jj][0], bf[2 * jj + 1][0], bf[2 * jj][1], bf[2 * jj + 1][1], addr);
            }
#pragma unroll
            for (int i16 = 0; i16 < 2; ++i16)
#pragma unroll
                for (int j = 0; j < 16; ++j)
                    mma_f16(c[i16][j], af[i16], bf[j]);
        }
    }

    float* Sp = g_S + (size_t)(h * NB + b) * HD * HD;
#pragma unroll
    for (int i16 = 0; i16 < 2; ++i16) {
        const int d0 = wm + i16 * 16 + r;
#pragma unroll
        for (int j = 0; j < 16; ++j) {
            const int e = j * 8 + 2 * q;
            *(float2*)(Sp + (size_t)d0 * HD + e)       = make_float2(c[i16][j][0], c[i16][j][1]);
            *(float2*)(Sp + (size_t)(d0 + 8) * HD + e) = make_float2(c[i16][j][2], c[i16][j][3]);
        }
    }
}

// ---------------- attention stage B (fp32 scan) ----------------
__global__ void attn_scan(const float* __restrict__ kv_cache, const float* __restrict__ slope)
{
    const int g = blockIdx.x * 256 + threadIdx.x;
    const int h = g >> 14;
    const int e = g & 16383;
    const float dec = expf(-slope[h] * 256.0f);
    float c = kv_cache[(size_t)h * 16384 + e];
    const size_t base = (size_t)h * NB * 16384 + e;
#pragma unroll
    for (int b = 0; b < NB; ++b) {
        g_kvst[base + (size_t)b * 16384] = c;
        c = dec * c + g_S[base + (size_t)b * 16384];
    }
}

// ---------------- attention stage C1 (fp16 mma): O = qdec .* (q @ kvst) ----------------
__global__ __launch_bounds__(256, 1)
void attn_ointer_mma(const float* __restrict__ slope)
{
    extern __shared__ __align__(128) __half asm_sm[];
    __half (*Qs)[KP2]  = (__half(*)[KP2])asm_sm;
    __half (*KVs)[KP2] = (__half(*)[KP2])(asm_sm + 256 * KP2);

    const int b = blockIdx.x;
    const int h = blockIdx.y;
    const float s = slope[h];

    const int t = threadIdx.x;
    const int w = t >> 5, lane = t & 31;
    const int wm = w * 32;
    const int r = lane >> 2, q = lane & 3;
    const int lrow = (lane & 7) + ((lane >> 3) & 1) * 8;
    const int lcol = (lane >> 4) * 8;
    const int trow = (lane & 7) + ((lane >> 4) & 1) * 8;
    const int tcol = ((lane >> 3) & 1) * 8;

    const __half* qbase = g_qkvh + (size_t)(b * BLK) * QKVW + h * 384;
    const float*  st    = g_kvst + (size_t)(h * NB + b) * HD * HD;

#pragma unroll
    for (int it = 0; it < 16; ++it) {
        int id = t + 256 * it;
        int row = id >> 4, c16 = id & 15;
        uint4 v = *(const uint4*)(qbase + (size_t)row * QKVW + c16 * 8);
        *(uint4*)&Qs[row][c16 * 8] = v;
    }
#pragma unroll
    for (int it = 0; it < 16; ++it) {
        int id = t + 256 * it;
        int row = id >> 5, c4 = id & 31;
        float4 f = *(const float4*)(st + (size_t)row * HD + c4 * 4);
        __half2 h0 = __floats2half2_rn(f.x, f.y);
        __half2 h1 = __floats2half2_rn(f.z, f.w);
        uint2 o; o.x = *(uint32_t*)&h0; o.y = *(uint32_t*)&h1;
        *(uint2*)&KVs[row][c4 * 4] = o;
    }
    __syncthreads();

    const uint32_t sQ  = smem_u32(Qs);
    const uint32_t sKV = smem_u32(KVs);

    float c[2][16][4];
#pragma unroll
    for (int i = 0; i < 2; ++i)
#pragma unroll
        for (int j = 0; j < 16; ++j)
#pragma unroll
            for (int p = 0; p < 4; ++p) c[i][j][p] = 0.0f;

#pragma unroll
    for (int kc = 0; kc < 8; ++kc) {
        uint32_t af[2][4], bf[16][2];
#pragma unroll
        for (int i16 = 0; i16 < 2; ++i16) {
            uint32_t addr = sQ + ((wm + i16 * 16 + lrow) * KP2 + kc * 16 + lcol) * 2;
            ldsm_x4(af[i16][0], af[i16][1], af[i16][2], af[i16][3], addr);
        }
#pragma unroll
        for (int jj = 0; jj < 8; ++jj) {
            uint32_t addr = sKV + ((kc * 16 + trow) * KP2 + jj * 16 + tcol) * 2;
            ldsm_x4_t(bf[2 * jj][0], bf[2 * jj + 1][0], bf[2 * jj][1], bf[2 * jj + 1][1], addr);
        }
#pragma unroll
        for (int i16 = 0; i16 < 2; ++i16)
#pragma unroll
            for (int j = 0; j < 16; ++j)
                mma_f16(c[i16][j], af[i16], bf[j]);
    }

    float* hbase = g_hidden + (size_t)(b * BLK) * INNER + h * HD;
#pragma unroll
    for (int i16 = 0; i16 < 2; ++i16) {
        const int m0 = wm + i16 * 16 + r;
        const float qd0 = expf(-s * (float)(m0 + 1));
        const float qd8 = expf(-s * (float)(m0 + 9));
#pragma unroll
        for (int j = 0; j < 16; ++j) {
            const int e = j * 8 + 2 * q;
            *(float2*)(hbase + (size_t)m0 * INNER + e) =
                make_float2(c[i16][j][0] * qd0, c[i16][j][1] * qd0);
            *(float2*)(hbase + (size_t)(m0 + 8) * INNER + e) =
                make_float2(c[i16][j][2] * qd8, c[i16][j][3] * qd8);
        }
    }
}

// ---------------- attention stage C2 (fp16 mma): O += tril-decay(q k^T) v ----------------
// One CTA per (b,h); Q/K/V fully resident in smem; warp w handles 16-row
// m-tiles {w, 15-w} -> exactly 5 causal 64-col chunks per warp (balanced).
__global__ __launch_bounds__(256, 1)
void attn_ointra_mma(const float* __restrict__ slope)
{
    extern __shared__ __align__(128) __half osm[];
    const uint32_t sQ = smem_u32(osm);
    const uint32_t sK = sQ + 256 * KP2 * 2;
    const uint32_t sV = sK + 256 * KP2 * 2;
    const uint32_t sP = sV + 256 * KP2 * 2;

    const int b = blockIdx.x;
    const int h = blockIdx.y;
    const float s = slope[h];

    const int t = threadIdx.x;
    const int w = t >> 5, lane = t & 31;
    const int r = lane >> 2, q = lane & 3;
    const int lrow = (lane & 7) + ((lane >> 3) & 1) * 8;
    const int lcol = (lane >> 4) * 8;
    const int trow = (lane & 7) + ((lane >> 4) & 1) * 8;
    const int tcol = ((lane >> 3) & 1) * 8;

    const __half* qkv = g_qkvh + (size_t)(b * BLK) * QKVW + h * 384;

    // stage Q, K, V (each 256 rows x 128 halfs)
    __half* Qs = (__half*)osm;
    __half* Ks = Qs + 256 * KP2;
    __half* Vs = Ks + 256 * KP2;
#pragma unroll
    for (int it = 0; it < 16; ++it) {
        int id = t + 256 * it;
        int row = id >> 4, c16 = id & 15;
        *(uint4*)&Qs[row * KP2 + c16 * 8] = *(const uint4*)(qkv + (size_t)row * QKVW + c16 * 8);
        *(uint4*)&Ks[row * KP2 + c16 * 8] = *(const uint4*)(qkv + 128 + (size_t)row * QKVW + c16 * 8);
        *(uint4*)&Vs[row * KP2 + c16 * 8] = *(const uint4*)(qkv + 256 + (size_t)row * QKVW + c16 * 8);
    }
    __syncthreads();

    const uint32_t sPw = sP + w * 16 * PSTR * 2;    // per-warp P buffer
    __half* Pw = (__half*)(osm) + (sPw - sQ) / 2;

#pragma unroll
    for (int tt = 0; tt < 2; ++tt) {
        const int mt = (tt == 0) ? w : (15 - w);    // 16-row m-tile index
        const int mrow = mt * 16 + r;

        float oc[16][4];
#pragma unroll
        for (int j = 0; j < 16; ++j)
#pragma unroll
            for (int p = 0; p < 4; ++p) oc[j][p] = 0.0f;

        const int nchunks = mt / 4 + 1;             // causal 64-col chunks
        for (int nt = 0; nt < nchunks; ++nt) {
            // ---- P = Q K^T (16 x 64) ----
            float pc[8][4];
#pragma unroll
            for (int j = 0; j < 8; ++j)
#pragma unroll
                for (int p = 0; p < 4; ++p) pc[j][p] = 0.0f;

#pragma unroll
            for (int kc = 0; kc < 8; ++kc) {
                uint32_t qa[4], kb[8][2];
                ldsm_x4(qa[0], qa[1], qa[2], qa[3],
                        sQ + ((mt * 16 + lrow) * KP2 + kc * 16 + lcol) * 2);
#pragma unroll
                for (int j16 = 0; j16 < 4; ++j16) {
                    ldsm_x4(kb[2 * j16][0], kb[2 * j16 + 1][0],
                            kb[2 * j16][1], kb[2 * j16 + 1][1],
                            sK + ((nt * 64 + j16 * 16 + lrow) * KP2 + kc * 16 + lcol) * 2);
                }
#pragma unroll
                for (int j = 0; j < 8; ++j) mma_f16(pc[j], qa, kb[j]);
            }

            // ---- decay mask + convert -> per-warp P smem ----
#pragma unroll
            for (int j = 0; j < 8; ++j) {
                const int n0 = nt * 64 + j * 8 + 2 * q;
                float f0 = (mrow >= n0)         ? pc[j][0] * expf(-s * (float)(mrow - n0))         : 0.0f;
                float f1 = (mrow >= n0 + 1)     ? pc[j][1] * expf(-s * (float)(mrow - n0 - 1))     : 0.0f;
                float f2 = (mrow + 8 >= n0)     ? pc[j][2] * expf(-s * (float)(mrow + 8 - n0))     : 0.0f;
                float f3 = (mrow + 8 >= n0 + 1) ? pc[j][3] * expf(-s * (float)(mrow + 8 - n0 - 1)) : 0.0f;
                __half2 h0 = __floats2half2_rn(f0, f1);
                __half2 h1 = __floats2half2_rn(f2, f3);
                *(__half2*)&Pw[r * PSTR + j * 8 + 2 * q]       = h0;
                *(__half2*)&Pw[(r + 8) * PSTR + j * 8 + 2 * q] = h1;
            }
            __syncwarp();

            // ---- O += P V (16 x 128) ----
#pragma unroll
            for (int ks = 0; ks < 4; ++ks) {
                uint32_t pa[4], vb[16][2];
                ldsm_x4(pa[0], pa[1], pa[2], pa[3],
                        sPw + (lrow * PSTR + ks * 16 + lcol) * 2);
#pragma unroll
                for (int jj = 0; jj < 8; ++jj) {
                    ldsm_x4_t(vb[2 * jj][0], vb[2 * jj + 1][0],
                              vb[2 * jj][1], vb[2 * jj + 1][1],
                              sV + ((nt * 64 + ks * 16 + trow) * KP2 + jj * 16 + tcol) * 2);
                }
#pragma unroll
                for (int j = 0; j < 16; ++j) mma_f16(oc[j], pa, vb[j]);
            }
            __syncwarp();
        }

        // accumulate into g_hidden (o_inter already there)
        float* hb = g_hidden + (size_t)(b * BLK + mt * 16) * INNER + h * HD;
#pragma unroll
        for (int j = 0; j < 16; ++j) {
            const int e = j * 8 + 2 * q;
            float2* p0 = (float2*)(hb + (size_t)r * INNER + e);
            float2* p1 = (float2*)(hb + (size_t)(r + 8) * INNER + e);
            float2 v0 = *p0, v1 = *p1;
            v0.x += oc[j][0]; v0.y += oc[j][1];
            v1.x += oc[j][2]; v1.y += oc[j][3];
            *p0 = v0; *p1 = v1;
        }
    }
}

// ---------------- RMSNorm * weight * gate -> fp16 ----------------
__global__ __launch_bounds__(256)
void rmsnorm_gate(const float* __restrict__ nw)
{
    const int m = blockIdx.x;
    const int t = threadIdx.x;
    const float* hrow = g_hidden + (size_t)m * INNER;
    const float* grow = g_gate + (size_t)m * INNER;
    __half* orow = g_ghalf + (size_t)m * INNER;

    float ss = 0.0f;
    for (int i = t; i < INNER / 4; i += 256) {
        float4 h4 = *(const float4*)(hrow + i * 4);
        ss += h4.x * h4.x + h4.y * h4.y + h4.z * h4.z + h4.w * h4.w;
    }
    __shared__ float red[256];
    red[t] = ss;
    __syncthreads();
    for (int s2 = 128; s2 > 0; s2 >>= 1) {
        if (t < s2) red[t] += red[t + s2];
        __syncthreads();
    }
    const float rs = rsqrtf(red[0] / (float)INNER + EPS_RMS);

    for (int i = t; i < INNER / 4; i += 256) {
        float4 h4 = *(const float4*)(hrow + i * 4);
        float4 g4 = *(const float4*)(grow + i * 4);
        float4 w4 = *(const float4*)(nw + i * 4);
        __half2 o0 = __floats2half2_rn(g4.x * (h4.x * rs * w4.x),
                                       g4.y * (h4.y * rs * w4.y));
        __half2 o1 = __floats2half2_rn(g4.z * (h4.z * rs * w4.z),
                                       g4.w * (h4.w * rs * w4.w));
        uint2 o;
        o.x = *(uint32_t*)&o0; o.y = *(uint32_t*)&o1;
        *(uint2*)(orow + i * 4) = o;
    }
}

// ---------------- launcher ----------------
extern "C" void kernel_launch(void* const* d_in, const int* in_sizes, int n_in,
                              void* d_out, int out_size)
{
    (void)in_sizes; (void)n_in; (void)out_size;
    const float* x     = (const float*)d_in[0];
    const float* wqkv  = (const float*)d_in[1];
    const float* wgate = (const float*)d_in[2];
    const float* wout  = (const float*)d_in[3];
    const float* nw    = (const float*)d_in[4];
    const float* kvc   = (const float*)d_in[5];
    const float* slope = (const float*)d_in[6];
    float* out = (float*)d_out;

    float *p_gate = nullptr;
    __half *p_qkvh = nullptr, *p_xh = nullptr, *p_wqkvh = nullptr,
           *p_wgateh = nullptr, *p_wouth = nullptr, *p_ghalf = nullptr;
    cudaGetSymbolAddress((void**)&p_qkvh, g_qkvh);
    cudaGetSymbolAddress((void**)&p_gate, g_gate);
    cudaGetSymbolAddress((void**)&p_xh, g_xh);
    cudaGetSymbolAddress((void**)&p_wqkvh, g_wqkvh);
    cudaGetSymbolAddress((void**)&p_wgateh, g_wgateh);
    cudaGetSymbolAddress((void**)&p_wouth, g_wouth);
    cudaGetSymbolAddress((void**)&p_ghalf, g_ghalf);

    cudaFuncSetAttribute((const void*)gemm_mma<EPI_SILU, false, true>,  cudaFuncAttributeMaxDynamicSharedMemorySize, GEMM_SMEM);
    cudaFuncSetAttribute((const void*)gemm_mma<EPI_SIGM, true, false>,  cudaFuncAttributeMaxDynamicSharedMemorySize, GEMM_SMEM);
    cudaFuncSetAttribute((const void*)gemm_mma<EPI_NONE, true, false>,  cudaFuncAttributeMaxDynamicSharedMemorySize, GEMM_SMEM);
    cudaFuncSetAttribute((const void*)attn_ointer_mma, cudaFuncAttributeMaxDynamicSharedMemorySize, OINTER_SMEM);
    cudaFuncSetAttribute((const void*)attn_ointra_mma, cudaFuncAttributeMaxDynamicSharedMemorySize, OINTRA_SMEM);

    // fp32 -> fp16 conversions
    cvt_f16_kernel<<<(SEQ * HDIM / 8 + 255) / 256, 256>>>(x, p_xh, SEQ * HDIM / 8);
    cvt_f16_kernel<<<(QKVW * HDIM / 8 + 255) / 256, 256>>>(wqkv, p_wqkvh, QKVW * HDIM / 8);
    cvt_f16_kernel<<<(INNER * HDIM / 8 + 255) / 256, 256>>>(wgate, p_wgateh, INNER * HDIM / 8);
    cvt_f16_kernel<<<(HDIM * INNER / 8 + 255) / 256, 256>>>(wout, p_wouth, HDIM * INNER / 8);

    // qkv = silu(x @ w_qkv^T) -> fp16 only
    gemm_mma<EPI_SILU, false, true><<<dim3(QKVW / BN, SEQ / BM), NTHR, GEMM_SMEM>>>(p_xh, p_wqkvh, nullptr, p_qkvh, QKVW);
    // gate = sigmoid(x @ w_gate^T)
    gemm_mma<EPI_SIGM, true, false><<<dim3(INNER / BN, SEQ / BM), NTHR, GEMM_SMEM>>>(p_xh, p_wgateh, p_gate, nullptr, INNER);

    // lightning attention
    attn_kvblocks_mma<<<dim3(NB, NH), 128>>>(slope);
    attn_scan<<<(NH * HD * HD) / 256, 256>>>(kvc, slope);
    attn_ointer_mma<<<dim3(NB, NH), 256, OINTER_SMEM>>>(slope);
    attn_ointra_mma<<<dim3(NB, NH), 256, OINTRA_SMEM>>>(slope);

    // rmsnorm * weight * gate -> fp16
    rmsnorm_gate<<<SEQ, 256>>>(nw);

    // out = (gate * normed) @ w_out^T
    gemm_mma<EPI_NONE, true, false><<<dim3(HDIM / BN, SEQ / BM), NTHR, GEMM_SMEM>>>(p_ghalf, p_wouth, out, nullptr, HDIM);
}

// round 10
// speedup vs baseline: 1.3762x; 1.0362x over previous
#include <cuda_runtime.h>
#include <cuda_fp16.h>
#include <math.h>
#include <stdint.h>

#define SEQ   4096
#define HDIM  4096
#define INNER 4096
#define NH    32
#define HD    128
#define BLK   256
#define NB    16
#define QKVW  12288
#define EPS_RMS 1e-5f

#define GK    4096
#define BM    128
#define BN    128
#define BK    64
#define NTHR  128
#define KTILES (GK / BK)    // 64
#define KPADH 72
#define STGH_A (128 * KPADH)
#define STAGE_BYTES (2 * STGH_A * 2)    // 36864
#define NSTG  3
#define GEMM_SMEM (NSTG * STAGE_BYTES)  // 110592 -> 2 CTAs/SM

#define KP2   136
#define OINTER_SMEM ((256 + 128) * KP2 * 2)   // 104448

#define PSTR  72
#define OINTRA_SMEM (3 * 256 * KP2 * 2 + 8 * 16 * PSTR * 2)   // 227328

// ---------------- scratch ----------------
__device__ __half g_qkvh[(size_t)SEQ * QKVW];
__device__ float  g_hidden[(size_t)SEQ * INNER];
__device__ __half g_gateh[(size_t)SEQ * INNER];   // fp16 sigmoid gate
__device__ float  g_S[(size_t)NH * NB * HD * HD];
__device__ float  g_kvst[(size_t)NH * NB * HD * HD];
__device__ __half g_xh[(size_t)SEQ * HDIM];
__device__ __half g_wqkvh[(size_t)QKVW * HDIM];
__device__ __half g_wgateh[(size_t)INNER * HDIM];
__device__ __half g_wouth[(size_t)HDIM * INNER];
__device__ __half g_ghalf[(size_t)SEQ * INNER];

// ---------------- helpers ----------------
__device__ __forceinline__ uint32_t smem_u32(const void* p) {
    uint32_t a;
    asm("{ .reg .u64 t; cvta.to.shared.u64 t, %1; cvt.u32.u64 %0, t; }" : "=r"(a) : "l"(p));
    return a;
}

__device__ __forceinline__ void cp_async16(uint32_t dst, const void* src) {
    asm volatile("cp.async.cg.shared.global [%0], [%1], 16;" :: "r"(dst), "l"(src));
}
#define CP_COMMIT() asm volatile("cp.async.commit_group;" ::: "memory")
#define CP_WAIT(n)  asm volatile("cp.async.wait_group %0;" :: "n"(n) : "memory")

__device__ __forceinline__ void ldsm_x4(uint32_t& r0, uint32_t& r1, uint32_t& r2, uint32_t& r3,
                                        uint32_t addr) {
    asm volatile("ldmatrix.sync.aligned.m8n8.x4.shared.b16 {%0,%1,%2,%3}, [%4];"
        : "=r"(r0), "=r"(r1), "=r"(r2), "=r"(r3) : "r"(addr));
}
__device__ __forceinline__ void ldsm_x4_t(uint32_t& r0, uint32_t& r1, uint32_t& r2, uint32_t& r3,
                                          uint32_t addr) {
    asm volatile("ldmatrix.sync.aligned.m8n8.x4.trans.shared.b16 {%0,%1,%2,%3}, [%4];"
        : "=r"(r0), "=r"(r1), "=r"(r2), "=r"(r3) : "r"(addr));
}

__device__ __forceinline__ void mma_f16(float* c, const uint32_t* a, const uint32_t* b) {
    asm volatile(
        "mma.sync.aligned.m16n8k16.row.col.f32.f16.f16.f32 "
        "{%0,%1,%2,%3}, {%4,%5,%6,%7}, {%8,%9}, {%0,%1,%2,%3};"
        : "+f"(c[0]), "+f"(c[1]), "+f"(c[2]), "+f"(c[3])
        : "r"(a[0]), "r"(a[1]), "r"(a[2]), "r"(a[3]), "r"(b[0]), "r"(b[1]));
}

__device__ __forceinline__ float silu_f(float v)  { return v / (1.0f + expf(-v)); }
__device__ __forceinline__ float sigm_f(float v)  { return 1.0f / (1.0f + expf(-v)); }

// ---------------- fused fp32 -> fp16 conversion (all four arrays, one launch) ----------------
#define N1 (SEQ * HDIM / 8)
#define N2 (QKVW * HDIM / 8)
#define N3 (INNER * HDIM / 8)
#define N4 (HDIM * INNER / 8)
__global__ __launch_bounds__(256)
void cvt_all_kernel(const float* __restrict__ x,  const float* __restrict__ wq,
                    const float* __restrict__ wg, const float* __restrict__ wo,
                    __half* __restrict__ xh,  __half* __restrict__ wqh,
                    __half* __restrict__ wgh, __half* __restrict__ woh)
{
    int i = blockIdx.x * 256 + threadIdx.x;
    const float* in; __half* out; int j;
    if (i < N1)                { in = x;  out = xh;  j = i; }
    else if (i < N1 + N2)      { in = wq; out = wqh; j = i - N1; }
    else if (i < N1 + N2 + N3) { in = wg; out = wgh; j = i - N1 - N2; }
    else                       { in = wo; out = woh; j = i - N1 - N2 - N3; }
    float4 v0 = ((const float4*)in)[j * 2];
    float4 v1 = ((const float4*)in)[j * 2 + 1];
    __half2 h0 = __floats2half2_rn(v0.x, v0.y);
    __half2 h1 = __floats2half2_rn(v0.z, v0.w);
    __half2 h2 = __floats2half2_rn(v1.x, v1.y);
    __half2 h3 = __floats2half2_rn(v1.z, v1.w);
    uint4 o;
    o.x = *(uint32_t*)&h0; o.y = *(uint32_t*)&h1;
    o.z = *(uint32_t*)&h2; o.w = *(uint32_t*)&h3;
    ((uint4*)out)[j] = o;
}

// ---------------- GEMM mainloop core (round-6 proven) ----------------
__device__ __forceinline__ void g_load_stage(uint32_t sbase, int slot, int s,
                                             const __half* __restrict__ Ab,
                                             const __half* __restrict__ Bb, int t)
{
    const uint32_t stA = sbase + slot * STAGE_BYTES;
    const uint32_t stB = stA + STGH_A * 2;
    const __half* ga = Ab + (size_t)s * BK;
    const __half* gb = Bb + (size_t)s * BK;
#pragma unroll
    for (int i = 0; i < 8; ++i) {
        int id = t + NTHR * i;
        int row = id >> 3, c = id & 7;
        cp_async16(stA + (row * KPADH + c * 8) * 2, ga + (size_t)row * GK + c * 8);
    }
#pragma unroll
    for (int i = 0; i < 8; ++i) {
        int id = t + NTHR * i;
        int row = id >> 3, c = id & 7;
        cp_async16(stB + (row * KPADH + c * 8) * 2, gb + (size_t)row * GK + c * 8);
    }
}

__device__ __forceinline__ void gemm_mainloop(uint32_t sbase, const __half* Ab,
                                              const __half* Bb, int t, int wm, int wn,
                                              int r, int q, float c[4][8][4])
{
#pragma unroll
    for (int i = 0; i < 4; ++i)
#pragma unroll
        for (int j = 0; j < 8; ++j)
#pragma unroll
            for (int p = 0; p < 4; ++p) c[i][j][p] = 0.0f;

    g_load_stage(sbase, 0, 0, Ab, Bb, t); CP_COMMIT();
    g_load_stage(sbase, 1, 1, Ab, Bb, t); CP_COMMIT();

    const __half* smem = (const __half*)0;  // unused; addresses via sbase loads below
    (void)smem;

    for (int s = 0; s < KTILES; ++s) {
        const int slot = s % NSTG;
        CP_WAIT(1);
        __syncthreads();

        if (s + 2 < KTILES) {
            g_load_stage(sbase, (s + 2) % NSTG, s + 2, Ab, Bb, t);
        }
        CP_COMMIT();

        // fragment loads via scalar LDS (proven layout); compute smem pointers from sbase
#pragma unroll
        for (int ks = 0; ks < 4; ++ks) {
            const int k0 = ks * 16;
            uint32_t af[4][4], bf[8][2];
            const uint32_t sA = sbase + slot * STAGE_BYTES;
            const uint32_t sB = sA + STGH_A * 2;
#pragma unroll
            for (int i = 0; i < 4; ++i) {
                uint32_t ap = sA + ((wm + i * 16 + r) * KPADH + k0 + 2 * q) * 2;
                asm volatile("ld.shared.b32 %0, [%1];"      : "=r"(af[i][0]) : "r"(ap));
                asm volatile("ld.shared.b32 %0, [%1];"      : "=r"(af[i][1]) : "r"(ap + 8 * KPADH * 2));
                asm volatile("ld.shared.b32 %0, [%1];"      : "=r"(af[i][2]) : "r"(ap + 16));
                asm volatile("ld.shared.b32 %0, [%1];"      : "=r"(af[i][3]) : "r"(ap + 8 * KPADH * 2 + 16));
            }
#pragma unroll
            for (int j = 0; j < 8; ++j) {
                uint32_t bp = sB + ((wn + j * 8 + r) * KPADH + k0 + 2 * q) * 2;
                asm volatile("ld.shared.b32 %0, [%1];" : "=r"(bf[j][0]) : "r"(bp));
                asm volatile("ld.shared.b32 %0, [%1];" : "=r"(bf[j][1]) : "r"(bp + 16));
            }
#pragma unroll
            for (int i = 0; i < 4; ++i)
#pragma unroll
                for (int j = 0; j < 8; ++j)
                    mma_f16(c[i][j], af[i], bf[j]);
        }
    }
}

// ---------------- fused GEMM1+GEMM2: qkv (silu->fp16) and gate (sigmoid->fp16) ----------------
__global__ __launch_bounds__(NTHR, 2)
void gemm_qkvgate(const __half* __restrict__ A,
                  const __half* __restrict__ Bq, const __half* __restrict__ Bg)
{
    extern __shared__ __align__(128) __half smem[];
    const uint32_t sbase = smem_u32(smem);
    const int t    = threadIdx.x;
    const int wid  = t >> 5;
    const int lane = t & 31;
    const int bm = blockIdx.y * BM;
    const int bn = blockIdx.x * BN;

    const bool is_q = (bn < QKVW);
    const int  cbase = is_q ? bn : (bn - QKVW);
    const __half* Bb = (is_q ? Bq : Bg) + (size_t)cbase * GK;
    __half* Ch = (is_q ? g_qkvh : g_gateh);
    const int Ntot = is_q ? QKVW : INNER;
    const __half* Ab = A + (size_t)bm * GK;

    const int wm = (wid & 1) * 64;
    const int wn = (wid >> 1) * 64;
    const int r  = lane >> 2;
    const int q  = lane & 3;

    float c[4][8][4];
    gemm_mainloop(sbase, Ab, Bb, t, wm, wn, r, q, c);

#pragma unroll
    for (int i = 0; i < 4; ++i) {
        const int row0 = bm + wm + i * 16 + r;
#pragma unroll
        for (int j = 0; j < 8; ++j) {
            const int col = cbase + wn + j * 8 + 2 * q;
            float f0, f1, f2, f3;
            if (is_q) {
                f0 = silu_f(c[i][j][0]); f1 = silu_f(c[i][j][1]);
                f2 = silu_f(c[i][j][2]); f3 = silu_f(c[i][j][3]);
            } else {
                f0 = sigm_f(c[i][j][0]); f1 = sigm_f(c[i][j][1]);
                f2 = sigm_f(c[i][j][2]); f3 = sigm_f(c[i][j][3]);
            }
            __half2 h0 = __floats2half2_rn(f0, f1);
            __half2 h1 = __floats2half2_rn(f2, f3);
            *(__half2*)(Ch + (size_t)row0 * Ntot + col)       = h0;
            *(__half2*)(Ch + (size_t)(row0 + 8) * Ntot + col) = h1;
        }
    }
}

// ---------------- GEMM3: out = (gate*normed) @ w_out^T (fp32 out) ----------------
__global__ __launch_bounds__(NTHR, 2)
void gemm_out(const __half* __restrict__ A, const __half* __restrict__ B,
              float* __restrict__ C)
{
    extern __shared__ __align__(128) __half smem[];
    const uint32_t sbase = smem_u32(smem);
    const int t    = threadIdx.x;
    const int wid  = t >> 5;
    const int lane = t & 31;
    const int bm = blockIdx.y * BM;
    const int bn = blockIdx.x * BN;
    const __half* Ab = A + (size_t)bm * GK;
    const __half* Bb = B + (size_t)bn * GK;

    const int wm = (wid & 1) * 64;
    const int wn = (wid >> 1) * 64;
    const int r  = lane >> 2;
    const int q  = lane & 3;

    float c[4][8][4];
    gemm_mainloop(sbase, Ab, Bb, t, wm, wn, r, q, c);

#pragma unroll
    for (int i = 0; i < 4; ++i) {
        const int row0 = bm + wm + i * 16 + r;
#pragma unroll
        for (int j = 0; j < 8; ++j) {
            const int col = bn + wn + j * 8 + 2 * q;
            *(float2*)(C + (size_t)row0 * HDIM + col)       = make_float2(c[i][j][0], c[i][j][1]);
            *(float2*)(C + (size_t)(row0 + 8) * HDIM + col) = make_float2(c[i][j][2], c[i][j][3]);
        }
    }
}

// ---------------- attention stage A (fp16 mma) ----------------
__global__ __launch_bounds__(128)
void attn_kvblocks_mma(const float* __restrict__ slope)
{
    const int b = blockIdx.x;
    const int h = blockIdx.y;
    const float s = slope[h];

    __shared__ __half Ks[64][KP2];
    __shared__ __half Vs[64][KP2];

    const int t = threadIdx.x;
    const int w = t >> 5, lane = t & 31;
    const int wm = w * 32;
    const int r = lane >> 2, q = lane & 3;
    const int trow = (lane & 7) + ((lane >> 4) & 1) * 8;
    const int tcol = ((lane >> 3) & 1) * 8;

    const __half* kbase = g_qkvh + (size_t)(b * BLK) * QKVW + h * 384 + 128;
    const __half* vbase = kbase + 128;

    const uint32_t sK = smem_u32(Ks);
    const uint32_t sV = smem_u32(Vs);

    float c[2][16][4];
#pragma unroll
    for (int i = 0; i < 2; ++i)
#pragma unroll
        for (int j = 0; j < 16; ++j)
#pragma unroll
            for (int p = 0; p < 4; ++p) c[i][j][p] = 0.0f;

    for (int ch = 0; ch < 4; ++ch) {
        __syncthreads();
#pragma unroll
        for (int it = 0; it < 8; ++it) {
            int id = t + 128 * it;
            int row = id >> 4;
            int c16 = id & 15;
            int i = ch * 64 + row;
            float kd = expf(-s * (float)(255 - i));
            uint4 k4 = *(const uint4*)(kbase + (size_t)i * QKVW + c16 * 8);
            __half2* hp = (__half2*)&k4;
#pragma unroll
            for (int z = 0; z < 4; ++z) {
                float2 f = __half22float2(hp[z]);
                hp[z] = __floats2half2_rn(f.x * kd, f.y * kd);
            }
            *(uint4*)&Ks[row][c16 * 8] = k4;
            uint4 v4 = *(const uint4*)(vbase + (size_t)i * QKVW + c16 * 8);
            *(uint4*)&Vs[row][c16 * 8] = v4;
        }
        __syncthreads();

#pragma unroll
        for (int kc = 0; kc < 4; ++kc) {
            uint32_t af[2][4], bf[16][2];
#pragma unroll
            for (int i16 = 0; i16 < 2; ++i16) {
                uint32_t addr = sK + ((kc * 16 + trow) * KP2 + wm + i16 * 16 + tcol) * 2;
                ldsm_x4_t(af[i16][0], af[i16][1], af[i16][2], af[i16][3], addr);
            }
#pragma unroll
            for (int jj = 0; jj < 8; ++jj) {
                uint32_t addr = sV + ((kc * 16 + trow) * KP2 + jj * 16 + tcol) * 2;
                ldsm_x4_t(bf[2 * jj][0], bf[2 * jj + 1][0], bf[2 * jj][1], bf[2 * jj + 1][1], addr);
            }
#pragma unroll
            for (int i16 = 0; i16 < 2; ++i16)
#pragma unroll
                for (int j = 0; j < 16; ++j)
                    mma_f16(c[i16][j], af[i16], bf[j]);
        }
    }

    float* Sp = g_S + (size_t)(h * NB + b) * HD * HD;
#pragma unroll
    for (int i16 = 0; i16 < 2; ++i16) {
        const int d0 = wm + i16 * 16 + r;
#pragma unroll
        for (int j = 0; j < 16; ++j) {
            const int e = j * 8 + 2 * q;
            *(float2*)(Sp + (size_t)d0 * HD + e)       = make_float2(c[i16][j][0], c[i16][j][1]);
            *(float2*)(Sp + (size_t)(d0 + 8) * HD + e) = make_float2(c[i16][j][2], c[i16][j][3]);
        }
    }
}

// ---------------- attention stage B (fp32 scan) ----------------
__global__ void attn_scan(const float* __restrict__ kv_cache, const float* __restrict__ slope)
{
    const int g = blockIdx.x * 256 + threadIdx.x;
    const int h = g >> 14;
    const int e = g & 16383;
    const float dec = expf(-slope[h] * 256.0f);
    float c = kv_cache[(size_t)h * 16384 + e];
    const size_t base = (size_t)h * NB * 16384 + e;
#pragma unroll
    for (int b = 0; b < NB; ++b) {
        g_kvst[base + (size_t)b * 16384] = c;
        c = dec * c + g_S[base + (size_t)b * 16384];
    }
}

// ---------------- attention stage C1 (fp16 mma) ----------------
__global__ __launch_bounds__(256, 1)
void attn_ointer_mma(const float* __restrict__ slope)
{
    extern __shared__ __align__(128) __half asm_sm[];
    __half (*Qs)[KP2]  = (__half(*)[KP2])asm_sm;
    __half (*KVs)[KP2] = (__half(*)[KP2])(asm_sm + 256 * KP2);

    const int b = blockIdx.x;
    const int h = blockIdx.y;
    const float s = slope[h];

    const int t = threadIdx.x;
    const int w = t >> 5, lane = t & 31;
    const int wm = w * 32;
    const int r = lane >> 2, q = lane & 3;
    const int lrow = (lane & 7) + ((lane >> 3) & 1) * 8;
    const int lcol = (lane >> 4) * 8;
    const int trow = (lane & 7) + ((lane >> 4) & 1) * 8;
    const int tcol = ((lane >> 3) & 1) * 8;

    const __half* qbase = g_qkvh + (size_t)(b * BLK) * QKVW + h * 384;
    const float*  st    = g_kvst + (size_t)(h * NB + b) * HD * HD;

#pragma unroll
    for (int it = 0; it < 16; ++it) {
        int id = t + 256 * it;
        int row = id >> 4, c16 = id & 15;
        uint4 v = *(const uint4*)(qbase + (size_t)row * QKVW + c16 * 8);
        *(uint4*)&Qs[row][c16 * 8] = v;
    }
#pragma unroll
    for (int it = 0; it < 16; ++it) {
        int id = t + 256 * it;
        int row = id >> 5, c4 = id & 31;
        float4 f = *(const float4*)(st + (size_t)row * HD + c4 * 4);
        __half2 h0 = __floats2half2_rn(f.x, f.y);
        __half2 h1 = __floats2half2_rn(f.z, f.w);
        uint2 o; o.x = *(uint32_t*)&h0; o.y = *(uint32_t*)&h1;
        *(uint2*)&KVs[row][c4 * 4] = o;
    }
    __syncthreads();

    const uint32_t sQ  = smem_u32(Qs);
    const uint32_t sKV = smem_u32(KVs);

    float c[2][16][4];
#pragma unroll
    for (int i = 0; i < 2; ++i)
#pragma unroll
        for (int j = 0; j < 16; ++j)
#pragma unroll
            for (int p = 0; p < 4; ++p) c[i][j][p] = 0.0f;

#pragma unroll
    for (int kc = 0; kc < 8; ++kc) {
        uint32_t af[2][4], bf[16][2];
#pragma unroll
        for (int i16 = 0; i16 < 2; ++i16) {
            uint32_t addr = sQ + ((wm + i16 * 16 + lrow) * KP2 + kc * 16 + lcol) * 2;
            ldsm_x4(af[i16][0], af[i16][1], af[i16][2], af[i16][3], addr);
        }
#pragma unroll
        for (int jj = 0; jj < 8; ++jj) {
            uint32_t addr = sKV + ((kc * 16 + trow) * KP2 + jj * 16 + tcol) * 2;
            ldsm_x4_t(bf[2 * jj][0], bf[2 * jj + 1][0], bf[2 * jj][1], bf[2 * jj + 1][1], addr);
        }
#pragma unroll
        for (int i16 = 0; i16 < 2; ++i16)
#pragma unroll
            for (int j = 0; j < 16; ++j)
                mma_f16(c[i16][j], af[i16], bf[j]);
    }

    float* hbase = g_hidden + (size_t)(b * BLK) * INNER + h * HD;
#pragma unroll
    for (int i16 = 0; i16 < 2; ++i16) {
        const int m0 = wm + i16 * 16 + r;
        const float qd0 = expf(-s * (float)(m0 + 1));
        const float qd8 = expf(-s * (float)(m0 + 9));
#pragma unroll
        for (int j = 0; j < 16; ++j) {
            const int e = j * 8 + 2 * q;
            *(float2*)(hbase + (size_t)m0 * INNER + e) =
                make_float2(c[i16][j][0] * qd0, c[i16][j][1] * qd0);
            *(float2*)(hbase + (size_t)(m0 + 8) * INNER + e) =
                make_float2(c[i16][j][2] * qd8, c[i16][j][3] * qd8);
        }
    }
}

// ---------------- attention stage C2 (fp16 mma) ----------------
__global__ __launch_bounds__(256, 1)
void attn_ointra_mma(const float* __restrict__ slope)
{
    extern __shared__ __align__(128) __half osm[];
    const uint32_t sQ = smem_u32(osm);
    const uint32_t sK = sQ + 256 * KP2 * 2;
    const uint32_t sV = sK + 256 * KP2 * 2;
    const uint32_t sP = sV + 256 * KP2 * 2;

    const int b = blockIdx.x;
    const int h = blockIdx.y;
    const float s = slope[h];

    const int t = threadIdx.x;
    const int w = t >> 5, lane = t & 31;
    const int r = lane >> 2, q = lane & 3;
    const int lrow = (lane & 7) + ((lane >> 3) & 1) * 8;
    const int lcol = (lane >> 4) * 8;
    const int trow = (lane & 7) + ((lane >> 4) & 1) * 8;
    const int tcol = ((lane >> 3) & 1) * 8;

    const __half* qkv = g_qkvh + (size_t)(b * BLK) * QKVW + h * 384;

    __half* Qs = (__half*)osm;
    __half* Ks = Qs + 256 * KP2;
    __half* Vs = Ks + 256 * KP2;
#pragma unroll
    for (int it = 0; it < 16; ++it) {
        int id = t + 256 * it;
        int row = id >> 4, c16 = id & 15;
        *(uint4*)&Qs[row * KP2 + c16 * 8] = *(const uint4*)(qkv + (size_t)row * QKVW + c16 * 8);
        *(uint4*)&Ks[row * KP2 + c16 * 8] = *(const uint4*)(qkv + 128 + (size_t)row * QKVW + c16 * 8);
        *(uint4*)&Vs[row * KP2 + c16 * 8] = *(const uint4*)(qkv + 256 + (size_t)row * QKVW + c16 * 8);
    }
    __syncthreads();

    const uint32_t sPw = sP + w * 16 * PSTR * 2;
    __half* Pw = (__half*)(osm) + (sPw - sQ) / 2;

#pragma unroll
    for (int tt = 0; tt < 2; ++tt) {
        const int mt = (tt == 0) ? w : (15 - w);
        const int mrow = mt * 16 + r;

        float oc[16][4];
#pragma unroll
        for (int j = 0; j < 16; ++j)
#pragma unroll
            for (int p = 0; p < 4; ++p) oc[j][p] = 0.0f;

        const int nchunks = mt / 4 + 1;
        for (int nt = 0; nt < nchunks; ++nt) {
            float pc[8][4];
#pragma unroll
            for (int j = 0; j < 8; ++j)
#pragma unroll
                for (int p = 0; p < 4; ++p) pc[j][p] = 0.0f;

#pragma unroll
            for (int kc = 0; kc < 8; ++kc) {
                uint32_t qa[4], kb[8][2];
                ldsm_x4(qa[0], qa[1], qa[2], qa[3],
                        sQ + ((mt * 16 + lrow) * KP2 + kc * 16 + lcol) * 2);
#pragma unroll
                for (int j16 = 0; j16 < 4; ++j16) {
                    ldsm_x4(kb[2 * j16][0], kb[2 * j16 + 1][0],
                            kb[2 * j16][1], kb[2 * j16 + 1][1],
                            sK + ((nt * 64 + j16 * 16 + lrow) * KP2 + kc * 16 + lcol) * 2);
                }
#pragma unroll
                for (int j = 0; j < 8; ++j) mma_f16(pc[j], qa, kb[j]);
            }

#pragma unroll
            for (int j = 0; j < 8; ++j) {
                const int n0 = nt * 64 + j * 8 + 2 * q;
                float f0 = (mrow >= n0)         ? pc[j][0] * expf(-s * (float)(mrow - n0))         : 0.0f;
                float f1 = (mrow >= n0 + 1)     ? pc[j][1] * expf(-s * (float)(mrow - n0 - 1))     : 0.0f;
                float f2 = (mrow + 8 >= n0)     ? pc[j][2] * expf(-s * (float)(mrow + 8 - n0))     : 0.0f;
                float f3 = (mrow + 8 >= n0 + 1) ? pc[j][3] * expf(-s * (float)(mrow + 8 - n0 - 1)) : 0.0f;
                __half2 h0 = __floats2half2_rn(f0, f1);
                __half2 h1 = __floats2half2_rn(f2, f3);
                *(__half2*)&Pw[r * PSTR + j * 8 + 2 * q]       = h0;
                *(__half2*)&Pw[(r + 8) * PSTR + j * 8 + 2 * q] = h1;
            }
            __syncwarp();

#pragma unroll
            for (int ks = 0; ks < 4; ++ks) {
                uint32_t pa[4], vb[16][2];
                ldsm_x4(pa[0], pa[1], pa[2], pa[3],
                        sPw + (lrow * PSTR + ks * 16 + lcol) * 2);
#pragma unroll
                for (int jj = 0; jj < 8; ++jj) {
                    ldsm_x4_t(vb[2 * jj][0], vb[2 * jj + 1][0],
                              vb[2 * jj][1], vb[2 * jj + 1][1],
                              sV + ((nt * 64 + ks * 16 + trow) * KP2 + jj * 16 + tcol) * 2);
                }
#pragma unroll
                for (int j = 0; j < 16; ++j) mma_f16(oc[j], pa, vb[j]);
            }
            __syncwarp();
        }

        float* hb = g_hidden + (size_t)(b * BLK + mt * 16) * INNER + h * HD;
#pragma unroll
        for (int j = 0; j < 16; ++j) {
            const int e = j * 8 + 2 * q;
            float2* p0 = (float2*)(hb + (size_t)r * INNER + e);
            float2* p1 = (float2*)(hb + (size_t)(r + 8) * INNER + e);
            float2 v0 = *p0, v1 = *p1;
            v0.x += oc[j][0]; v0.y += oc[j][1];
            v1.x += oc[j][2]; v1.y += oc[j][3];
            *p0 = v0; *p1 = v1;
        }
    }
}

// ---------------- RMSNorm * weight * gate(fp16) -> fp16 ----------------
__global__ __launch_bounds__(256)
void rmsnorm_gate(const float* __restrict__ nw)
{
    const int m = blockIdx.x;
    const int t = threadIdx.x;
    const float* hrow = g_hidden + (size_t)m * INNER;
    const __half* grow = g_gateh + (size_t)m * INNER;
    __half* orow = g_ghalf + (size_t)m * INNER;

    float ss = 0.0f;
    for (int i = t; i < INNER / 4; i += 256) {
        float4 h4 = *(const float4*)(hrow + i * 4);
        ss += h4.x * h4.x + h4.y * h4.y + h4.z * h4.z + h4.w * h4.w;
    }
    __shared__ float red[256];
    red[t] = ss;
    __syncthreads();
    for (int s2 = 128; s2 > 0; s2 >>= 1) {
        if (t < s2) red[t] += red[t + s2];
        __syncthreads();
    }
    const float rs = rsqrtf(red[0] / (float)INNER + EPS_RMS);

    for (int i = t; i < INNER / 4; i += 256) {
        float4 h4 = *(const float4*)(hrow + i * 4);
        uint2 g2 = *(const uint2*)(grow + i * 4);
        float2 g0 = __half22float2(*(__half2*)&g2.x);
        float2 g1 = __half22float2(*(__half2*)&g2.y);
        float4 w4 = *(const float4*)(nw + i * 4);
        __half2 o0 = __floats2half2_rn(g0.x * (h4.x * rs * w4.x),
                                       g0.y * (h4.y * rs * w4.y));
        __half2 o1 = __floats2half2_rn(g1.x * (h4.z * rs * w4.z),
                                       g1.y * (h4.w * rs * w4.w));
        uint2 o;
        o.x = *(uint32_t*)&o0; o.y = *(uint32_t*)&o1;
        *(uint2*)(orow + i * 4) = o;
    }
}

// ---------------- launcher ----------------
extern "C" void kernel_launch(void* const* d_in, const int* in_sizes, int n_in,
                              void* d_out, int out_size)
{
    (void)in_sizes; (void)n_in; (void)out_size;
    const float* x     = (const float*)d_in[0];
    const float* wqkv  = (const float*)d_in[1];
    const float* wgate = (const float*)d_in[2];
    const float* wout  = (const float*)d_in[3];
    const float* nw    = (const float*)d_in[4];
    const float* kvc   = (const float*)d_in[5];
    const float* slope = (const float*)d_in[6];
    float* out = (float*)d_out;

    __half *p_xh = nullptr, *p_wqkvh = nullptr, *p_wgateh = nullptr,
           *p_wouth = nullptr, *p_ghalf = nullptr;
    cudaGetSymbolAddress((void**)&p_xh, g_xh);
    cudaGetSymbolAddress((void**)&p_wqkvh, g_wqkvh);
    cudaGetSymbolAddress((void**)&p_wgateh, g_wgateh);
    cudaGetSymbolAddress((void**)&p_wouth, g_wouth);
    cudaGetSymbolAddress((void**)&p_ghalf, g_ghalf);

    cudaFuncSetAttribute((const void*)gemm_qkvgate, cudaFuncAttributeMaxDynamicSharedMemorySize, GEMM_SMEM);
    cudaFuncSetAttribute((const void*)gemm_out,     cudaFuncAttributeMaxDynamicSharedMemorySize, GEMM_SMEM);
    cudaFuncSetAttribute((const void*)attn_ointer_mma, cudaFuncAttributeMaxDynamicSharedMemorySize, OINTER_SMEM);
    cudaFuncSetAttribute((const void*)attn_ointra_mma, cudaFuncAttributeMaxDynamicSharedMemorySize, OINTRA_SMEM);

    // all fp32 -> fp16 conversions in one launch
    cvt_all_kernel<<<(N1 + N2 + N3 + N4) / 256, 256>>>(x, wqkv, wgate, wout,
                                                       p_xh, p_wqkvh, p_wgateh, p_wouth);

    // fused: qkv = silu(x@wqkv^T) -> fp16 ; gate = sigmoid(x@wgate^T) -> fp16
    gemm_qkvgate<<<dim3((QKVW + INNER) / BN, SEQ / BM), NTHR, GEMM_SMEM>>>(p_xh, p_wqkvh, p_wgateh);

    // lightning attention
    attn_kvblocks_mma<<<dim3(NB, NH), 128>>>(slope);
    attn_scan<<<(NH * HD * HD) / 256, 256>>>(kvc, slope);
    attn_ointer_mma<<<dim3(NB, NH), 256, OINTER_SMEM>>>(slope);
    attn_ointra_mma<<<dim3(NB, NH), 256, OINTRA_SMEM>>>(slope);

    // rmsnorm * weight * gate -> fp16
    rmsnorm_gate<<<SEQ, 256>>>(nw);

    // out = (gate * normed) @ w_out^T
    gemm_out<<<dim3(HDIM / BN, SEQ / BM), NTHR, GEMM_SMEM>>>(p_ghalf, p_wouth, out);
}

// round 11
// speedup vs baseline: 1.3975x; 1.0155x over previous
#include <cuda_runtime.h>
#include <cuda_fp16.h>
#include <math.h>
#include <stdint.h>

#define SEQ   4096
#define HDIM  4096
#define INNER 4096
#define NH    32
#define HD    128
#define BLK   256
#define NB    16
#define QKVW  12288
#define EPS_RMS 1e-5f

#define GK    4096
#define BM    128
#define BN    128
#define BK    64
#define NTHR  128
#define KTILES (GK / BK)    // 64
#define KPADH 72
#define STGH_A (128 * KPADH)
#define STAGE_BYTES (2 * STGH_A * 2)    // 36864
#define NSTG  3
#define GEMM_SMEM (NSTG * STAGE_BYTES)  // 110592 -> 2 CTAs/SM

#define KP2   136
#define OINTER_SMEM ((256 + 128) * KP2 * 2)   // 104448

#define PSTR  72
#define OINTRA_SMEM (3 * 256 * KP2 * 2 + 8 * 16 * PSTR * 2)   // 227328

// ---------------- scratch ----------------
__device__ __half g_qkvh[(size_t)SEQ * QKVW];
__device__ float  g_hidden[(size_t)SEQ * INNER];
__device__ __half g_gateh[(size_t)SEQ * INNER];
__device__ float  g_S[(size_t)NH * NB * HD * HD];
__device__ float  g_kvst[(size_t)NH * NB * HD * HD];
__device__ __half g_xh[(size_t)SEQ * HDIM];
__device__ __half g_wqkvh[(size_t)QKVW * HDIM];
__device__ __half g_wgateh[(size_t)INNER * HDIM];
__device__ __half g_wouth[(size_t)HDIM * INNER];
__device__ __half g_ghalf[(size_t)SEQ * INNER];

// ---------------- helpers ----------------
__device__ __forceinline__ uint32_t smem_u32(const void* p) {
    uint32_t a;
    asm("{ .reg .u64 t; cvta.to.shared.u64 t, %1; cvt.u32.u64 %0, t; }" : "=r"(a) : "l"(p));
    return a;
}

__device__ __forceinline__ void cp_async16(uint32_t dst, const void* src) {
    asm volatile("cp.async.cg.shared.global [%0], [%1], 16;" :: "r"(dst), "l"(src));
}
#define CP_COMMIT() asm volatile("cp.async.commit_group;" ::: "memory")
#define CP_WAIT(n)  asm volatile("cp.async.wait_group %0;" :: "n"(n) : "memory")

__device__ __forceinline__ void ldsm_x4(uint32_t& r0, uint32_t& r1, uint32_t& r2, uint32_t& r3,
                                        uint32_t addr) {
    asm volatile("ldmatrix.sync.aligned.m8n8.x4.shared.b16 {%0,%1,%2,%3}, [%4];"
        : "=r"(r0), "=r"(r1), "=r"(r2), "=r"(r3) : "r"(addr));
}
__device__ __forceinline__ void ldsm_x4_t(uint32_t& r0, uint32_t& r1, uint32_t& r2, uint32_t& r3,
                                          uint32_t addr) {
    asm volatile("ldmatrix.sync.aligned.m8n8.x4.trans.shared.b16 {%0,%1,%2,%3}, [%4];"
        : "=r"(r0), "=r"(r1), "=r"(r2), "=r"(r3) : "r"(addr));
}

__device__ __forceinline__ void mma_f16(float* c, const uint32_t* a, const uint32_t* b) {
    asm volatile(
        "mma.sync.aligned.m16n8k16.row.col.f32.f16.f16.f32 "
        "{%0,%1,%2,%3}, {%4,%5,%6,%7}, {%8,%9}, {%0,%1,%2,%3};"
        : "+f"(c[0]), "+f"(c[1]), "+f"(c[2]), "+f"(c[3])
        : "r"(a[0]), "r"(a[1]), "r"(a[2]), "r"(a[3]), "r"(b[0]), "r"(b[1]));
}

__device__ __forceinline__ float silu_f(float v)  { return v / (1.0f + expf(-v)); }
__device__ __forceinline__ float sigm_f(float v)  { return 1.0f / (1.0f + expf(-v)); }

// ---------------- fused fp32 -> fp16 conversion ----------------
#define N1 (SEQ * HDIM / 8)
#define N2 (QKVW * HDIM / 8)
#define N3 (INNER * HDIM / 8)
#define N4 (HDIM * INNER / 8)
__global__ __launch_bounds__(256)
void cvt_all_kernel(const float* __restrict__ x,  const float* __restrict__ wq,
                    const float* __restrict__ wg, const float* __restrict__ wo,
                    __half* __restrict__ xh,  __half* __restrict__ wqh,
                    __half* __restrict__ wgh, __half* __restrict__ woh)
{
    int i = blockIdx.x * 256 + threadIdx.x;
    const float* in; __half* out; int j;
    if (i < N1)                { in = x;  out = xh;  j = i; }
    else if (i < N1 + N2)      { in = wq; out = wqh; j = i - N1; }
    else if (i < N1 + N2 + N3) { in = wg; out = wgh; j = i - N1 - N2; }
    else                       { in = wo; out = woh; j = i - N1 - N2 - N3; }
    float4 v0 = ((const float4*)in)[j * 2];
    float4 v1 = ((const float4*)in)[j * 2 + 1];
    __half2 h0 = __floats2half2_rn(v0.x, v0.y);
    __half2 h1 = __floats2half2_rn(v0.z, v0.w);
    __half2 h2 = __floats2half2_rn(v1.x, v1.y);
    __half2 h3 = __floats2half2_rn(v1.z, v1.w);
    uint4 o;
    o.x = *(uint32_t*)&h0; o.y = *(uint32_t*)&h1;
    o.z = *(uint32_t*)&h2; o.w = *(uint32_t*)&h3;
    ((uint4*)out)[j] = o;
}

// ---------------- GEMM mainloop (fragment double-buffered) ----------------
__device__ __forceinline__ void g_load_stage(uint32_t sbase, int slot, int s,
                                             const __half* __restrict__ Ab,
                                             const __half* __restrict__ Bb, int t)
{
    const uint32_t stA = sbase + slot * STAGE_BYTES;
    const uint32_t stB = stA + STGH_A * 2;
    const __half* ga = Ab + (size_t)s * BK;
    const __half* gb = Bb + (size_t)s * BK;
#pragma unroll
    for (int i = 0; i < 8; ++i) {
        int id = t + NTHR * i;
        int row = id >> 3, c = id & 7;
        cp_async16(stA + (row * KPADH + c * 8) * 2, ga + (size_t)row * GK + c * 8);
    }
#pragma unroll
    for (int i = 0; i < 8; ++i) {
        int id = t + NTHR * i;
        int row = id >> 3, c = id & 7;
        cp_async16(stB + (row * KPADH + c * 8) * 2, gb + (size_t)row * GK + c * 8);
    }
}

__device__ __forceinline__ void lds_frags(uint32_t sA, uint32_t sB, int k0,
                                          int wm, int wn, int r, int q,
                                          uint32_t af[4][4], uint32_t bf[8][2])
{
#pragma unroll
    for (int i = 0; i < 4; ++i) {
        uint32_t ap = sA + ((wm + i * 16 + r) * KPADH + k0 + 2 * q) * 2;
        asm volatile("ld.shared.b32 %0, [%1];" : "=r"(af[i][0]) : "r"(ap));
        asm volatile("ld.shared.b32 %0, [%1];" : "=r"(af[i][1]) : "r"(ap + 8 * KPADH * 2));
        asm volatile("ld.shared.b32 %0, [%1];" : "=r"(af[i][2]) : "r"(ap + 16));
        asm volatile("ld.shared.b32 %0, [%1];" : "=r"(af[i][3]) : "r"(ap + 8 * KPADH * 2 + 16));
    }
#pragma unroll
    for (int j = 0; j < 8; ++j) {
        uint32_t bp = sB + ((wn + j * 8 + r) * KPADH + k0 + 2 * q) * 2;
        asm volatile("ld.shared.b32 %0, [%1];" : "=r"(bf[j][0]) : "r"(bp));
        asm volatile("ld.shared.b32 %0, [%1];" : "=r"(bf[j][1]) : "r"(bp + 16));
    }
}

__device__ __forceinline__ void gemm_mainloop(uint32_t sbase, const __half* Ab,
                                              const __half* Bb, int t, int wm, int wn,
                                              int r, int q, float c[4][8][4])
{
#pragma unroll
    for (int i = 0; i < 4; ++i)
#pragma unroll
        for (int j = 0; j < 8; ++j)
#pragma unroll
            for (int p = 0; p < 4; ++p) c[i][j][p] = 0.0f;

    g_load_stage(sbase, 0, 0, Ab, Bb, t); CP_COMMIT();
    g_load_stage(sbase, 1, 1, Ab, Bb, t); CP_COMMIT();

    for (int s = 0; s < KTILES; ++s) {
        const int slot = s % NSTG;
        CP_WAIT(1);
        __syncthreads();

        if (s + 2 < KTILES) {
            g_load_stage(sbase, (s + 2) % NSTG, s + 2, Ab, Bb, t);
        }
        CP_COMMIT();

        const uint32_t sA = sbase + slot * STAGE_BYTES;
        const uint32_t sB = sA + STGH_A * 2;

        uint32_t af[2][4][4], bf[2][8][2];
        lds_frags(sA, sB, 0, wm, wn, r, q, af[0], bf[0]);
#pragma unroll
        for (int ks = 0; ks < 4; ++ks) {
            if (ks < 3)
                lds_frags(sA, sB, (ks + 1) * 16, wm, wn, r, q,
                          af[(ks + 1) & 1], bf[(ks + 1) & 1]);
#pragma unroll
            for (int i = 0; i < 4; ++i)
#pragma unroll
                for (int j = 0; j < 8; ++j)
                    mma_f16(c[i][j], af[ks & 1][i], bf[ks & 1][j]);
        }
    }
}

// ---------------- fused GEMM1+GEMM2 ----------------
__global__ __launch_bounds__(NTHR, 2)
void gemm_qkvgate(const __half* __restrict__ A,
                  const __half* __restrict__ Bq, const __half* __restrict__ Bg)
{
    extern __shared__ __align__(128) __half smem[];
    const uint32_t sbase = smem_u32(smem);
    const int t    = threadIdx.x;
    const int wid  = t >> 5;
    const int lane = t & 31;
    const int bm = blockIdx.y * BM;
    const int bn = blockIdx.x * BN;

    const bool is_q = (bn < QKVW);
    const int  cbase = is_q ? bn : (bn - QKVW);
    const __half* Bb = (is_q ? Bq : Bg) + (size_t)cbase * GK;
    __half* Ch = (is_q ? g_qkvh : g_gateh);
    const int Ntot = is_q ? QKVW : INNER;
    const __half* Ab = A + (size_t)bm * GK;

    const int wm = (wid & 1) * 64;
    const int wn = (wid >> 1) * 64;
    const int r  = lane >> 2;
    const int q  = lane & 3;

    float c[4][8][4];
    gemm_mainloop(sbase, Ab, Bb, t, wm, wn, r, q, c);

#pragma unroll
    for (int i = 0; i < 4; ++i) {
        const int row0 = bm + wm + i * 16 + r;
#pragma unroll
        for (int j = 0; j < 8; ++j) {
            const int col = cbase + wn + j * 8 + 2 * q;
            float f0, f1, f2, f3;
            if (is_q) {
                f0 = silu_f(c[i][j][0]); f1 = silu_f(c[i][j][1]);
                f2 = silu_f(c[i][j][2]); f3 = silu_f(c[i][j][3]);
            } else {
                f0 = sigm_f(c[i][j][0]); f1 = sigm_f(c[i][j][1]);
                f2 = sigm_f(c[i][j][2]); f3 = sigm_f(c[i][j][3]);
            }
            __half2 h0 = __floats2half2_rn(f0, f1);
            __half2 h1 = __floats2half2_rn(f2, f3);
            *(__half2*)(Ch + (size_t)row0 * Ntot + col)       = h0;
            *(__half2*)(Ch + (size_t)(row0 + 8) * Ntot + col) = h1;
        }
    }
}

// ---------------- GEMM3 ----------------
__global__ __launch_bounds__(NTHR, 2)
void gemm_out(const __half* __restrict__ A, const __half* __restrict__ B,
              float* __restrict__ C)
{
    extern __shared__ __align__(128) __half smem[];
    const uint32_t sbase = smem_u32(smem);
    const int t    = threadIdx.x;
    const int wid  = t >> 5;
    const int lane = t & 31;
    const int bm = blockIdx.y * BM;
    const int bn = blockIdx.x * BN;
    const __half* Ab = A + (size_t)bm * GK;
    const __half* Bb = B + (size_t)bn * GK;

    const int wm = (wid & 1) * 64;
    const int wn = (wid >> 1) * 64;
    const int r  = lane >> 2;
    const int q  = lane & 3;

    float c[4][8][4];
    gemm_mainloop(sbase, Ab, Bb, t, wm, wn, r, q, c);

#pragma unroll
    for (int i = 0; i < 4; ++i) {
        const int row0 = bm + wm + i * 16 + r;
#pragma unroll
        for (int j = 0; j < 8; ++j) {
            const int col = bn + wn + j * 8 + 2 * q;
            *(float2*)(C + (size_t)row0 * HDIM + col)       = make_float2(c[i][j][0], c[i][j][1]);
            *(float2*)(C + (size_t)(row0 + 8) * HDIM + col) = make_float2(c[i][j][2], c[i][j][3]);
        }
    }
}

// ---------------- attention stage A (fp16 mma) ----------------
__global__ __launch_bounds__(128)
void attn_kvblocks_mma(const float* __restrict__ slope)
{
    const int b = blockIdx.x;
    const int h = blockIdx.y;
    const float s = slope[h];

    __shared__ __half Ks[64][KP2];
    __shared__ __half Vs[64][KP2];

    const int t = threadIdx.x;
    const int w = t >> 5, lane = t & 31;
    const int wm = w * 32;
    const int r = lane >> 2, q = lane & 3;
    const int trow = (lane & 7) + ((lane >> 4) & 1) * 8;
    const int tcol = ((lane >> 3) & 1) * 8;

    const __half* kbase = g_qkvh + (size_t)(b * BLK) * QKVW + h * 384 + 128;
    const __half* vbase = kbase + 128;

    const uint32_t sK = smem_u32(Ks);
    const uint32_t sV = smem_u32(Vs);

    float c[2][16][4];
#pragma unroll
    for (int i = 0; i < 2; ++i)
#pragma unroll
        for (int j = 0; j < 16; ++j)
#pragma unroll
            for (int p = 0; p < 4; ++p) c[i][j][p] = 0.0f;

    for (int ch = 0; ch < 4; ++ch) {
        __syncthreads();
#pragma unroll
        for (int it = 0; it < 8; ++it) {
            int id = t + 128 * it;
            int row = id >> 4;
            int c16 = id & 15;
            int i = ch * 64 + row;
            float kd = expf(-s * (float)(255 - i));
            uint4 k4 = *(const uint4*)(kbase + (size_t)i * QKVW + c16 * 8);
            __half2* hp = (__half2*)&k4;
#pragma unroll
            for (int z = 0; z < 4; ++z) {
                float2 f = __half22float2(hp[z]);
                hp[z] = __floats2half2_rn(f.x * kd, f.y * kd);
            }
            *(uint4*)&Ks[row][c16 * 8] = k4;
            uint4 v4 = *(const uint4*)(vbase + (size_t)i * QKVW + c16 * 8);
            *(uint4*)&Vs[row][c16 * 8] = v4;
        }
        __syncthreads();

#pragma unroll
        for (int kc = 0; kc < 4; ++kc) {
            uint32_t af[2][4], bf[16][2];
#pragma unroll
            for (int i16 = 0; i16 < 2; ++i16) {
                uint32_t addr = sK + ((kc * 16 + trow) * KP2 + wm + i16 * 16 + tcol) * 2;
                ldsm_x4_t(af[i16][0], af[i16][1], af[i16][2], af[i16][3], addr);
            }
#pragma unroll
            for (int jj = 0; jj < 8; ++jj) {
                uint32_t addr = sV + ((kc * 16 + trow) * KP2 + jj * 16 + tcol) * 2;
                ldsm_x4_t(bf[2 * jj][0], bf[2 * jj + 1][0], bf[2 * jj][1], bf[2 * jj + 1][1], addr);
            }
#pragma unroll
            for (int i16 = 0; i16 < 2; ++i16)
#pragma unroll
                for (int j = 0; j < 16; ++j)
                    mma_f16(c[i16][j], af[i16], bf[j]);
        }
    }

    float* Sp = g_S + (size_t)(h * NB + b) * HD * HD;
#pragma unroll
    for (int i16 = 0; i16 < 2; ++i16) {
        const int d0 = wm + i16 * 16 + r;
#pragma unroll
        for (int j = 0; j < 16; ++j) {
            const int e = j * 8 + 2 * q;
            *(float2*)(Sp + (size_t)d0 * HD + e)       = make_float2(c[i16][j][0], c[i16][j][1]);
            *(float2*)(Sp + (size_t)(d0 + 8) * HD + e) = make_float2(c[i16][j][2], c[i16][j][3]);
        }
    }
}

// ---------------- attention stage B (fp32 scan, MLP prefetch) ----------------
__global__ void attn_scan(const float* __restrict__ kv_cache, const float* __restrict__ slope)
{
    const int g = blockIdx.x * 256 + threadIdx.x;
    const int h = g >> 14;
    const int e = g & 16383;
    const float dec = expf(-slope[h] * 256.0f);
    const size_t base = (size_t)h * NB * 16384 + e;

    float sv[NB];
#pragma unroll
    for (int b = 0; b < NB; ++b)
        sv[b] = g_S[base + (size_t)b * 16384];

    float c = kv_cache[(size_t)h * 16384 + e];
#pragma unroll
    for (int b = 0; b < NB; ++b) {
        g_kvst[base + (size_t)b * 16384] = c;
        c = dec * c + sv[b];
    }
}

// ---------------- attention stage C1 (fp16 mma) ----------------
__global__ __launch_bounds__(256, 1)
void attn_ointer_mma(const float* __restrict__ slope)
{
    extern __shared__ __align__(128) __half asm_sm[];
    __half (*Qs)[KP2]  = (__half(*)[KP2])asm_sm;
    __half (*KVs)[KP2] = (__half(*)[KP2])(asm_sm + 256 * KP2);

    const int b = blockIdx.x;
    const int h = blockIdx.y;
    const float s = slope[h];

    const int t = threadIdx.x;
    const int w = t >> 5, lane = t & 31;
    const int wm = w * 32;
    const int r = lane >> 2, q = lane & 3;
    const int lrow = (lane & 7) + ((lane >> 3) & 1) * 8;
    const int lcol = (lane >> 4) * 8;
    const int trow = (lane & 7) + ((lane >> 4) & 1) * 8;
    const int tcol = ((lane >> 3) & 1) * 8;

    const __half* qbase = g_qkvh + (size_t)(b * BLK) * QKVW + h * 384;
    const float*  st    = g_kvst + (size_t)(h * NB + b) * HD * HD;

#pragma unroll
    for (int it = 0; it < 16; ++it) {
        int id = t + 256 * it;
        int row = id >> 4, c16 = id & 15;
        uint4 v = *(const uint4*)(qbase + (size_t)row * QKVW + c16 * 8);
        *(uint4*)&Qs[row][c16 * 8] = v;
    }
#pragma unroll
    for (int it = 0; it < 16; ++it) {
        int id = t + 256 * it;
        int row = id >> 5, c4 = id & 31;
        float4 f = *(const float4*)(st + (size_t)row * HD + c4 * 4);
        __half2 h0 = __floats2half2_rn(f.x, f.y);
        __half2 h1 = __floats2half2_rn(f.z, f.w);
        uint2 o; o.x = *(uint32_t*)&h0; o.y = *(uint32_t*)&h1;
        *(uint2*)&KVs[row][c4 * 4] = o;
    }
    __syncthreads();

    const uint32_t sQ  = smem_u32(Qs);
    const uint32_t sKV = smem_u32(KVs);

    float c[2][16][4];
#pragma unroll
    for (int i = 0; i < 2; ++i)
#pragma unroll
        for (int j = 0; j < 16; ++j)
#pragma unroll
            for (int p = 0; p < 4; ++p) c[i][j][p] = 0.0f;

#pragma unroll
    for (int kc = 0; kc < 8; ++kc) {
        uint32_t af[2][4], bf[16][2];
#pragma unroll
        for (int i16 = 0; i16 < 2; ++i16) {
            uint32_t addr = sQ + ((wm + i16 * 16 + lrow) * KP2 + kc * 16 + lcol) * 2;
            ldsm_x4(af[i16][0], af[i16][1], af[i16][2], af[i16][3], addr);
        }
#pragma unroll
        for (int jj = 0; jj < 8; ++jj) {
            uint32_t addr = sKV + ((kc * 16 + trow) * KP2 + jj * 16 + tcol) * 2;
            ldsm_x4_t(bf[2 * jj][0], bf[2 * jj + 1][0], bf[2 * jj][1], bf[2 * jj + 1][1], addr);
        }
#pragma unroll
        for (int i16 = 0; i16 < 2; ++i16)
#pragma unroll
            for (int j = 0; j < 16; ++j)
                mma_f16(c[i16][j], af[i16], bf[j]);
    }

    float* hbase = g_hidden + (size_t)(b * BLK) * INNER + h * HD;
#pragma unroll
    for (int i16 = 0; i16 < 2; ++i16) {
        const int m0 = wm + i16 * 16 + r;
        const float qd0 = expf(-s * (float)(m0 + 1));
        const float qd8 = expf(-s * (float)(m0 + 9));
#pragma unroll
        for (int j = 0; j < 16; ++j) {
            const int e = j * 8 + 2 * q;
            *(float2*)(hbase + (size_t)m0 * INNER + e) =
                make_float2(c[i16][j][0] * qd0, c[i16][j][1] * qd0);
            *(float2*)(hbase + (size_t)(m0 + 8) * INNER + e) =
                make_float2(c[i16][j][2] * qd8, c[i16][j][3] * qd8);
        }
    }
}

// ---------------- attention stage C2 (fp16 mma) ----------------
__global__ __launch_bounds__(256, 1)
void attn_ointra_mma(const float* __restrict__ slope)
{
    extern __shared__ __align__(128) __half osm[];
    const uint32_t sQ = smem_u32(osm);
    const uint32_t sK = sQ + 256 * KP2 * 2;
    const uint32_t sV = sK + 256 * KP2 * 2;
    const uint32_t sP = sV + 256 * KP2 * 2;

    const int b = blockIdx.x;
    const int h = blockIdx.y;
    const float s = slope[h];

    const int t = threadIdx.x;
    const int w = t >> 5, lane = t & 31;
    const int r = lane >> 2, q = lane & 3;
    const int lrow = (lane & 7) + ((lane >> 3) & 1) * 8;
    const int lcol = (lane >> 4) * 8;
    const int trow = (lane & 7) + ((lane >> 4) & 1) * 8;
    const int tcol = ((lane >> 3) & 1) * 8;

    const __half* qkv = g_qkvh + (size_t)(b * BLK) * QKVW + h * 384;

    __half* Qs = (__half*)osm;
    __half* Ks = Qs + 256 * KP2;
    __half* Vs = Ks + 256 * KP2;
#pragma unroll
    for (int it = 0; it < 16; ++it) {
        int id = t + 256 * it;
        int row = id >> 4, c16 = id & 15;
        *(uint4*)&Qs[row * KP2 + c16 * 8] = *(const uint4*)(qkv + (size_t)row * QKVW + c16 * 8);
        *(uint4*)&Ks[row * KP2 + c16 * 8] = *(const uint4*)(qkv + 128 + (size_t)row * QKVW + c16 * 8);
        *(uint4*)&Vs[row * KP2 + c16 * 8] = *(const uint4*)(qkv + 256 + (size_t)row * QKVW + c16 * 8);
    }
    __syncthreads();

    const uint32_t sPw = sP + w * 16 * PSTR * 2;
    __half* Pw = (__half*)(osm) + (sPw - sQ) / 2;

#pragma unroll
    for (int tt = 0; tt < 2; ++tt) {
        const int mt = (tt == 0) ? w : (15 - w);
        const int mrow = mt * 16 + r;

        float oc[16][4];
#pragma unroll
        for (int j = 0; j < 16; ++j)
#pragma unroll
            for (int p = 0; p < 4; ++p) oc[j][p] = 0.0f;

        const int nchunks = mt / 4 + 1;
        for (int nt = 0; nt < nchunks; ++nt) {
            float pc[8][4];
#pragma unroll
            for (int j = 0; j < 8; ++j)
#pragma unroll
                for (int p = 0; p < 4; ++p) pc[j][p] = 0.0f;

#pragma unroll
            for (int kc = 0; kc < 8; ++kc) {
                uint32_t qa[4], kb[8][2];
                ldsm_x4(qa[0], qa[1], qa[2], qa[3],
                        sQ + ((mt * 16 + lrow) * KP2 + kc * 16 + lcol) * 2);
#pragma unroll
                for (int j16 = 0; j16 < 4; ++j16) {
                    ldsm_x4(kb[2 * j16][0], kb[2 * j16 + 1][0],
                            kb[2 * j16][1], kb[2 * j16 + 1][1],
                            sK + ((nt * 64 + j16 * 16 + lrow) * KP2 + kc * 16 + lcol) * 2);
                }
#pragma unroll
                for (int j = 0; j < 8; ++j) mma_f16(pc[j], qa, kb[j]);
            }

#pragma unroll
            for (int j = 0; j < 8; ++j) {
                const int n0 = nt * 64 + j * 8 + 2 * q;
                float f0 = (mrow >= n0)         ? pc[j][0] * expf(-s * (float)(mrow - n0))         : 0.0f;
                float f1 = (mrow >= n0 + 1)     ? pc[j][1] * expf(-s * (float)(mrow - n0 - 1))     : 0.0f;
                float f2 = (mrow + 8 >= n0)     ? pc[j][2] * expf(-s * (float)(mrow + 8 - n0))     : 0.0f;
                float f3 = (mrow + 8 >= n0 + 1) ? pc[j][3] * expf(-s * (float)(mrow + 8 - n0 - 1)) : 0.0f;
                __half2 h0 = __floats2half2_rn(f0, f1);
                __half2 h1 = __floats2half2_rn(f2, f3);
                *(__half2*)&Pw[r * PSTR + j * 8 + 2 * q]       = h0;
                *(__half2*)&Pw[(r + 8) * PSTR + j * 8 + 2 * q] = h1;
            }
            __syncwarp();

#pragma unroll
            for (int ks = 0; ks < 4; ++ks) {
                uint32_t pa[4], vb[16][2];
                ldsm_x4(pa[0], pa[1], pa[2], pa[3],
                        sPw + (lrow * PSTR + ks * 16 + lcol) * 2);
#pragma unroll
                for (int jj = 0; jj < 8; ++jj) {
                    ldsm_x4_t(vb[2 * jj][0], vb[2 * jj + 1][0],
                              vb[2 * jj][1], vb[2 * jj + 1][1],
                              sV + ((nt * 64 + ks * 16 + trow) * KP2 + jj * 16 + tcol) * 2);
                }
#pragma unroll
                for (int j = 0; j < 16; ++j) mma_f16(oc[j], pa, vb[j]);
            }
            __syncwarp();
        }

        float* hb = g_hidden + (size_t)(b * BLK + mt * 16) * INNER + h * HD;
#pragma unroll
        for (int j = 0; j < 16; ++j) {
            const int e = j * 8 + 2 * q;
            float2* p0 = (float2*)(hb + (size_t)r * INNER + e);
            float2* p1 = (float2*)(hb + (size_t)(r + 8) * INNER + e);
            float2 v0 = *p0, v1 = *p1;
            v0.x += oc[j][0]; v0.y += oc[j][1];
            v1.x += oc[j][2]; v1.y += oc[j][3];
            *p0 = v0; *p1 = v1;
        }
    }
}

// ---------------- RMSNorm * weight * gate(fp16) -> fp16 ----------------
__global__ __launch_bounds__(256)
void rmsnorm_gate(const float* __restrict__ nw)
{
    const int m = blockIdx.x;
    const int t = threadIdx.x;
    const float* hrow = g_hidden + (size_t)m * INNER;
    const __half* grow = g_gateh + (size_t)m * INNER;
    __half* orow = g_ghalf + (size_t)m * INNER;

    float ss = 0.0f;
    for (int i = t; i < INNER / 4; i += 256) {
        float4 h4 = *(const float4*)(hrow + i * 4);
        ss += h4.x * h4.x + h4.y * h4.y + h4.z * h4.z + h4.w * h4.w;
    }
    __shared__ float red[256];
    red[t] = ss;
    __syncthreads();
    for (int s2 = 128; s2 > 0; s2 >>= 1) {
        if (t < s2) red[t] += red[t + s2];
        __syncthreads();
    }
    const float rs = rsqrtf(red[0] / (float)INNER + EPS_RMS);

    for (int i = t; i < INNER / 4; i += 256) {
        float4 h4 = *(const float4*)(hrow + i * 4);
        uint2 g2 = *(const uint2*)(grow + i * 4);
        float2 g0 = __half22float2(*(__half2*)&g2.x);
        float2 g1 = __half22float2(*(__half2*)&g2.y);
        float4 w4 = *(const float4*)(nw + i * 4);
        __half2 o0 = __floats2half2_rn(g0.x * (h4.x * rs * w4.x),
                                       g0.y * (h4.y * rs * w4.y));
        __half2 o1 = __floats2half2_rn(g1.x * (h4.z * rs * w4.z),
                                       g1.y * (h4.w * rs * w4.w));
        uint2 o;
        o.x = *(uint32_t*)&o0; o.y = *(uint32_t*)&o1;
        *(uint2*)(orow + i * 4) = o;
    }
}

// ---------------- launcher ----------------
extern "C" void kernel_launch(void* const* d_in, const int* in_sizes, int n_in,
                              void* d_out, int out_size)
{
    (void)in_sizes; (void)n_in; (void)out_size;
    const float* x     = (const float*)d_in[0];
    const float* wqkv  = (const float*)d_in[1];
    const float* wgate = (const float*)d_in[2];
    const float* wout  = (const float*)d_in[3];
    const float* nw    = (const float*)d_in[4];
    const float* kvc   = (const float*)d_in[5];
    const float* slope = (const float*)d_in[6];
    float* out = (float*)d_out;

    __half *p_xh = nullptr, *p_wqkvh = nullptr, *p_wgateh = nullptr,
           *p_wouth = nullptr, *p_ghalf = nullptr;
    cudaGetSymbolAddress((void**)&p_xh, g_xh);
    cudaGetSymbolAddress((void**)&p_wqkvh, g_wqkvh);
    cudaGetSymbolAddress((void**)&p_wgateh, g_wgateh);
    cudaGetSymbolAddress((void**)&p_wouth, g_wouth);
    cudaGetSymbolAddress((void**)&p_ghalf, g_ghalf);

    cudaFuncSetAttribute((const void*)gemm_qkvgate, cudaFuncAttributeMaxDynamicSharedMemorySize, GEMM_SMEM);
    cudaFuncSetAttribute((const void*)gemm_out,     cudaFuncAttributeMaxDynamicSharedMemorySize, GEMM_SMEM);
    cudaFuncSetAttribute((const void*)attn_ointer_mma, cudaFuncAttributeMaxDynamicSharedMemorySize, OINTER_SMEM);
    cudaFuncSetAttribute((const void*)attn_ointra_mma, cudaFuncAttributeMaxDynamicSharedMemorySize, OINTRA_SMEM);

    // all fp32 -> fp16 conversions in one launch
    cvt_all_kernel<<<(N1 + N2 + N3 + N4) / 256, 256>>>(x, wqkv, wgate, wout,
                                                       p_xh, p_wqkvh, p_wgateh, p_wouth);

    // fused: qkv = silu(x@wqkv^T) -> fp16 ; gate = sigmoid(x@wgate^T) -> fp16
    gemm_qkvgate<<<dim3((QKVW + INNER) / BN, SEQ / BM), NTHR, GEMM_SMEM>>>(p_xh, p_wqkvh, p_wgateh);

    // lightning attention
    attn_kvblocks_mma<<<dim3(NB, NH), 128>>>(slope);
    attn_scan<<<(NH * HD * HD) / 256, 256>>>(kvc, slope);
    attn_ointer_mma<<<dim3(NB, NH), 256, OINTER_SMEM>>>(slope);
    attn_ointra_mma<<<dim3(NB, NH), 256, OINTRA_SMEM>>>(slope);

    // rmsnorm * weight * gate -> fp16
    rmsnorm_gate<<<SEQ, 256>>>(nw);

    // out = (gate * normed) @ w_out^T
    gemm_out<<<dim3(HDIM / BN, SEQ / BM), NTHR, GEMM_SMEM>>>(p_ghalf, p_wouth, out);
}

// round 12
// speedup vs baseline: 1.4231x; 1.0183x over previous
#include <cuda_runtime.h>
#include <cuda_fp16.h>
#include <math.h>
#include <stdint.h>

#define SEQ   4096
#define HDIM  4096
#define INNER 4096
#define NH    32
#define HD    128
#define BLK   256
#define NB    16
#define QKVW  12288
#define EPS_RMS 1e-5f

#define GK    4096
#define BM    128
#define BN    128
#define BK    64
#define NTHR  128
#define KTILES (GK / BK)    // 64
#define KPADH 72
#define STGH_A (128 * KPADH)
#define STAGE_BYTES (2 * STGH_A * 2)    // 36864
#define NSTG  3
#define GEMM_SMEM (NSTG * STAGE_BYTES)  // 110592 -> 2 CTAs/SM

#define KP2   136
#define PSTR  72
#define ATTNOUT_SMEM (3 * 256 * KP2 * 2 + 8 * 16 * PSTR * 2)   // 227328

// ---------------- scratch ----------------
__device__ __half g_qkvh[(size_t)SEQ * QKVW];
__device__ float  g_hidden[(size_t)SEQ * INNER];
__device__ __half g_gateh[(size_t)SEQ * INNER];
__device__ float  g_S[(size_t)NH * NB * HD * HD];
__device__ __half g_kvsth[(size_t)NH * NB * HD * HD];   // fp16 KV states
__device__ __half g_xh[(size_t)SEQ * HDIM];
__device__ __half g_wqkvh[(size_t)QKVW * HDIM];
__device__ __half g_wgateh[(size_t)INNER * HDIM];
__device__ __half g_wouth[(size_t)HDIM * INNER];
__device__ __half g_ghalf[(size_t)SEQ * INNER];

// ---------------- helpers ----------------
__device__ __forceinline__ uint32_t smem_u32(const void* p) {
    uint32_t a;
    asm("{ .reg .u64 t; cvta.to.shared.u64 t, %1; cvt.u32.u64 %0, t; }" : "=r"(a) : "l"(p));
    return a;
}

__device__ __forceinline__ void cp_async16(uint32_t dst, const void* src) {
    asm volatile("cp.async.cg.shared.global [%0], [%1], 16;" :: "r"(dst), "l"(src));
}
#define CP_COMMIT() asm volatile("cp.async.commit_group;" ::: "memory")
#define CP_WAIT(n)  asm volatile("cp.async.wait_group %0;" :: "n"(n) : "memory")

__device__ __forceinline__ void ldsm_x4(uint32_t& r0, uint32_t& r1, uint32_t& r2, uint32_t& r3,
                                        uint32_t addr) {
    asm volatile("ldmatrix.sync.aligned.m8n8.x4.shared.b16 {%0,%1,%2,%3}, [%4];"
        : "=r"(r0), "=r"(r1), "=r"(r2), "=r"(r3) : "r"(addr));
}
__device__ __forceinline__ void ldsm_x4_t(uint32_t& r0, uint32_t& r1, uint32_t& r2, uint32_t& r3,
                                          uint32_t addr) {
    asm volatile("ldmatrix.sync.aligned.m8n8.x4.trans.shared.b16 {%0,%1,%2,%3}, [%4];"
        : "=r"(r0), "=r"(r1), "=r"(r2), "=r"(r3) : "r"(addr));
}

__device__ __forceinline__ void mma_f16(float* c, const uint32_t* a, const uint32_t* b) {
    asm volatile(
        "mma.sync.aligned.m16n8k16.row.col.f32.f16.f16.f32 "
        "{%0,%1,%2,%3}, {%4,%5,%6,%7}, {%8,%9}, {%0,%1,%2,%3};"
        : "+f"(c[0]), "+f"(c[1]), "+f"(c[2]), "+f"(c[3])
        : "r"(a[0]), "r"(a[1]), "r"(a[2]), "r"(a[3]), "r"(b[0]), "r"(b[1]));
}

__device__ __forceinline__ float silu_f(float v)  { return v / (1.0f + expf(-v)); }
__device__ __forceinline__ float sigm_f(float v)  { return 1.0f / (1.0f + expf(-v)); }

// ---------------- fused fp32 -> fp16 conversion ----------------
#define N1 (SEQ * HDIM / 8)
#define N2 (QKVW * HDIM / 8)
#define N3 (INNER * HDIM / 8)
#define N4 (HDIM * INNER / 8)
__global__ __launch_bounds__(256)
void cvt_all_kernel(const float* __restrict__ x,  const float* __restrict__ wq,
                    const float* __restrict__ wg, const float* __restrict__ wo,
                    __half* __restrict__ xh,  __half* __restrict__ wqh,
                    __half* __restrict__ wgh, __half* __restrict__ woh)
{
    int i = blockIdx.x * 256 + threadIdx.x;
    const float* in; __half* out; int j;
    if (i < N1)                { in = x;  out = xh;  j = i; }
    else if (i < N1 + N2)      { in = wq; out = wqh; j = i - N1; }
    else if (i < N1 + N2 + N3) { in = wg; out = wgh; j = i - N1 - N2; }
    else                       { in = wo; out = woh; j = i - N1 - N2 - N3; }
    float4 v0 = ((const float4*)in)[j * 2];
    float4 v1 = ((const float4*)in)[j * 2 + 1];
    __half2 h0 = __floats2half2_rn(v0.x, v0.y);
    __half2 h1 = __floats2half2_rn(v0.z, v0.w);
    __half2 h2 = __floats2half2_rn(v1.x, v1.y);
    __half2 h3 = __floats2half2_rn(v1.z, v1.w);
    uint4 o;
    o.x = *(uint32_t*)&h0; o.y = *(uint32_t*)&h1;
    o.z = *(uint32_t*)&h2; o.w = *(uint32_t*)&h3;
    ((uint4*)out)[j] = o;
}

// ---------------- GEMM mainloop (round-11 committed) ----------------
__device__ __forceinline__ void g_load_stage(uint32_t sbase, int slot, int s,
                                             const __half* __restrict__ Ab,
                                             const __half* __restrict__ Bb, int t)
{
    const uint32_t stA = sbase + slot * STAGE_BYTES;
    const uint32_t stB = stA + STGH_A * 2;
    const __half* ga = Ab + (size_t)s * BK;
    const __half* gb = Bb + (size_t)s * BK;
#pragma unroll
    for (int i = 0; i < 8; ++i) {
        int id = t + NTHR * i;
        int row = id >> 3, c = id & 7;
        cp_async16(stA + (row * KPADH + c * 8) * 2, ga + (size_t)row * GK + c * 8);
    }
#pragma unroll
    for (int i = 0; i < 8; ++i) {
        int id = t + NTHR * i;
        int row = id >> 3, c = id & 7;
        cp_async16(stB + (row * KPADH + c * 8) * 2, gb + (size_t)row * GK + c * 8);
    }
}

__device__ __forceinline__ void lds_frags(uint32_t sA, uint32_t sB, int k0,
                                          int wm, int wn, int r, int q,
                                          uint32_t af[4][4], uint32_t bf[8][2])
{
#pragma unroll
    for (int i = 0; i < 4; ++i) {
        uint32_t ap = sA + ((wm + i * 16 + r) * KPADH + k0 + 2 * q) * 2;
        asm volatile("ld.shared.b32 %0, [%1];" : "=r"(af[i][0]) : "r"(ap));
        asm volatile("ld.shared.b32 %0, [%1];" : "=r"(af[i][1]) : "r"(ap + 8 * KPADH * 2));
        asm volatile("ld.shared.b32 %0, [%1];" : "=r"(af[i][2]) : "r"(ap + 16));
        asm volatile("ld.shared.b32 %0, [%1];" : "=r"(af[i][3]) : "r"(ap + 8 * KPADH * 2 + 16));
    }
#pragma unroll
    for (int j = 0; j < 8; ++j) {
        uint32_t bp = sB + ((wn + j * 8 + r) * KPADH + k0 + 2 * q) * 2;
        asm volatile("ld.shared.b32 %0, [%1];" : "=r"(bf[j][0]) : "r"(bp));
        asm volatile("ld.shared.b32 %0, [%1];" : "=r"(bf[j][1]) : "r"(bp + 16));
    }
}

__device__ __forceinline__ void gemm_mainloop(uint32_t sbase, const __half* Ab,
                                              const __half* Bb, int t, int wm, int wn,
                                              int r, int q, float c[4][8][4])
{
#pragma unroll
    for (int i = 0; i < 4; ++i)
#pragma unroll
        for (int j = 0; j < 8; ++j)
#pragma unroll
            for (int p = 0; p < 4; ++p) c[i][j][p] = 0.0f;

    g_load_stage(sbase, 0, 0, Ab, Bb, t); CP_COMMIT();
    g_load_stage(sbase, 1, 1, Ab, Bb, t); CP_COMMIT();

    for (int s = 0; s < KTILES; ++s) {
        const int slot = s % NSTG;
        CP_WAIT(1);
        __syncthreads();

        if (s + 2 < KTILES) {
            g_load_stage(sbase, (s + 2) % NSTG, s + 2, Ab, Bb, t);
        }
        CP_COMMIT();

        const uint32_t sA = sbase + slot * STAGE_BYTES;
        const uint32_t sB = sA + STGH_A * 2;

        uint32_t af[2][4][4], bf[2][8][2];
        lds_frags(sA, sB, 0, wm, wn, r, q, af[0], bf[0]);
#pragma unroll
        for (int ks = 0; ks < 4; ++ks) {
            if (ks < 3)
                lds_frags(sA, sB, (ks + 1) * 16, wm, wn, r, q,
                          af[(ks + 1) & 1], bf[(ks + 1) & 1]);
#pragma unroll
            for (int i = 0; i < 4; ++i)
#pragma unroll
                for (int j = 0; j < 8; ++j)
                    mma_f16(c[i][j], af[ks & 1][i], bf[ks & 1][j]);
        }
    }
}

// ---------------- fused GEMM1+GEMM2 ----------------
__global__ __launch_bounds__(NTHR, 2)
void gemm_qkvgate(const __half* __restrict__ A,
                  const __half* __restrict__ Bq, const __half* __restrict__ Bg)
{
    extern __shared__ __align__(128) __half smem[];
    const uint32_t sbase = smem_u32(smem);
    const int t    = threadIdx.x;
    const int wid  = t >> 5;
    const int lane = t & 31;
    const int bm = blockIdx.y * BM;
    const int bn = blockIdx.x * BN;

    const bool is_q = (bn < QKVW);
    const int  cbase = is_q ? bn : (bn - QKVW);
    const __half* Bb = (is_q ? Bq : Bg) + (size_t)cbase * GK;
    __half* Ch = (is_q ? g_qkvh : g_gateh);
    const int Ntot = is_q ? QKVW : INNER;
    const __half* Ab = A + (size_t)bm * GK;

    const int wm = (wid & 1) * 64;
    const int wn = (wid >> 1) * 64;
    const int r  = lane >> 2;
    const int q  = lane & 3;

    float c[4][8][4];
    gemm_mainloop(sbase, Ab, Bb, t, wm, wn, r, q, c);

#pragma unroll
    for (int i = 0; i < 4; ++i) {
        const int row0 = bm + wm + i * 16 + r;
#pragma unroll
        for (int j = 0; j < 8; ++j) {
            const int col = cbase + wn + j * 8 + 2 * q;
            float f0, f1, f2, f3;
            if (is_q) {
                f0 = silu_f(c[i][j][0]); f1 = silu_f(c[i][j][1]);
                f2 = silu_f(c[i][j][2]); f3 = silu_f(c[i][j][3]);
            } else {
                f0 = sigm_f(c[i][j][0]); f1 = sigm_f(c[i][j][1]);
                f2 = sigm_f(c[i][j][2]); f3 = sigm_f(c[i][j][3]);
            }
            __half2 h0 = __floats2half2_rn(f0, f1);
            __half2 h1 = __floats2half2_rn(f2, f3);
            *(__half2*)(Ch + (size_t)row0 * Ntot + col)       = h0;
            *(__half2*)(Ch + (size_t)(row0 + 8) * Ntot + col) = h1;
        }
    }
}

// ---------------- GEMM3 ----------------
__global__ __launch_bounds__(NTHR, 2)
void gemm_out(const __half* __restrict__ A, const __half* __restrict__ B,
              float* __restrict__ C)
{
    extern __shared__ __align__(128) __half smem[];
    const uint32_t sbase = smem_u32(smem);
    const int t    = threadIdx.x;
    const int wid  = t >> 5;
    const int lane = t & 31;
    const int bm = blockIdx.y * BM;
    const int bn = blockIdx.x * BN;
    const __half* Ab = A + (size_t)bm * GK;
    const __half* Bb = B + (size_t)bn * GK;

    const int wm = (wid & 1) * 64;
    const int wn = (wid >> 1) * 64;
    const int r  = lane >> 2;
    const int q  = lane & 3;

    float c[4][8][4];
    gemm_mainloop(sbase, Ab, Bb, t, wm, wn, r, q, c);

#pragma unroll
    for (int i = 0; i < 4; ++i) {
        const int row0 = bm + wm + i * 16 + r;
#pragma unroll
        for (int j = 0; j < 8; ++j) {
            const int col = bn + wn + j * 8 + 2 * q;
            *(float2*)(C + (size_t)row0 * HDIM + col)       = make_float2(c[i][j][0], c[i][j][1]);
            *(float2*)(C + (size_t)(row0 + 8) * HDIM + col) = make_float2(c[i][j][2], c[i][j][3]);
        }
    }
}

// ---------------- attention stage A (fp16 mma) ----------------
__global__ __launch_bounds__(128)
void attn_kvblocks_mma(const float* __restrict__ slope)
{
    const int b = blockIdx.x;
    const int h = blockIdx.y;
    const float s = slope[h];

    __shared__ __half Ks[64][KP2];
    __shared__ __half Vs[64][KP2];

    const int t = threadIdx.x;
    const int w = t >> 5, lane = t & 31;
    const int wm = w * 32;
    const int r = lane >> 2, q = lane & 3;
    const int trow = (lane & 7) + ((lane >> 4) & 1) * 8;
    const int tcol = ((lane >> 3) & 1) * 8;

    const __half* kbase = g_qkvh + (size_t)(b * BLK) * QKVW + h * 384 + 128;
    const __half* vbase = kbase + 128;

    const uint32_t sK = smem_u32(Ks);
    const uint32_t sV = smem_u32(Vs);

    float c[2][16][4];
#pragma unroll
    for (int i = 0; i < 2; ++i)
#pragma unroll
        for (int j = 0; j < 16; ++j)
#pragma unroll
            for (int p = 0; p < 4; ++p) c[i][j][p] = 0.0f;

    for (int ch = 0; ch < 4; ++ch) {
        __syncthreads();
#pragma unroll
        for (int it = 0; it < 8; ++it) {
            int id = t + 128 * it;
            int row = id >> 4;
            int c16 = id & 15;
            int i = ch * 64 + row;
            float kd = expf(-s * (float)(255 - i));
            uint4 k4 = *(const uint4*)(kbase + (size_t)i * QKVW + c16 * 8);
            __half2* hp = (__half2*)&k4;
#pragma unroll
            for (int z = 0; z < 4; ++z) {
                float2 f = __half22float2(hp[z]);
                hp[z] = __floats2half2_rn(f.x * kd, f.y * kd);
            }
            *(uint4*)&Ks[row][c16 * 8] = k4;
            uint4 v4 = *(const uint4*)(vbase + (size_t)i * QKVW + c16 * 8);
            *(uint4*)&Vs[row][c16 * 8] = v4;
        }
        __syncthreads();

#pragma unroll
        for (int kc = 0; kc < 4; ++kc) {
            uint32_t af[2][4], bf[16][2];
#pragma unroll
            for (int i16 = 0; i16 < 2; ++i16) {
                uint32_t addr = sK + ((kc * 16 + trow) * KP2 + wm + i16 * 16 + tcol) * 2;
                ldsm_x4_t(af[i16][0], af[i16][1], af[i16][2], af[i16][3], addr);
            }
#pragma unroll
            for (int jj = 0; jj < 8; ++jj) {
                uint32_t addr = sV + ((kc * 16 + trow) * KP2 + jj * 16 + tcol) * 2;
                ldsm_x4_t(bf[2 * jj][0], bf[2 * jj + 1][0], bf[2 * jj][1], bf[2 * jj + 1][1], addr);
            }
#pragma unroll
            for (int i16 = 0; i16 < 2; ++i16)
#pragma unroll
                for (int j = 0; j < 16; ++j)
                    mma_f16(c[i16][j], af[i16], bf[j]);
        }
    }

    float* Sp = g_S + (size_t)(h * NB + b) * HD * HD;
#pragma unroll
    for (int i16 = 0; i16 < 2; ++i16) {
        const int d0 = wm + i16 * 16 + r;
#pragma unroll
        for (int j = 0; j < 16; ++j) {
            const int e = j * 8 + 2 * q;
            *(float2*)(Sp + (size_t)d0 * HD + e)       = make_float2(c[i16][j][0], c[i16][j][1]);
            *(float2*)(Sp + (size_t)(d0 + 8) * HD + e) = make_float2(c[i16][j][2], c[i16][j][3]);
        }
    }
}

// ---------------- attention stage B (fp32 scan, MLP prefetch, fp16 out) ----------------
__global__ void attn_scan(const float* __restrict__ kv_cache, const float* __restrict__ slope)
{
    const int g = blockIdx.x * 256 + threadIdx.x;
    const int h = g >> 14;
    const int e = g & 16383;
    const float dec = expf(-slope[h] * 256.0f);
    const size_t base = (size_t)h * NB * 16384 + e;

    float sv[NB];
#pragma unroll
    for (int b = 0; b < NB; ++b)
        sv[b] = g_S[base + (size_t)b * 16384];

    float c = kv_cache[(size_t)h * 16384 + e];
#pragma unroll
    for (int b = 0; b < NB; ++b) {
        g_kvsth[base + (size_t)b * 16384] = __float2half_rn(c);
        c = dec * c + sv[b];
    }
}

// ---------------- fused attention output: o_inter + o_intra, single store ----------------
// One CTA per (b,h); 8 warps; warp w owns 16-row m-tiles {w, 15-w}.
// Phase A: Q + KVstate(fp16) staged; oc = qdec .* (q @ KV) per m-tile.
// Phase B: K,V staged (K overwrites KV slot); oc += tril-decay(q k^T) v; store.
__global__ __launch_bounds__(256, 1)
void attn_out_mma(const float* __restrict__ slope)
{
    extern __shared__ __align__(128) __half osm[];
    const uint32_t sQ = smem_u32(osm);
    const uint32_t sK = sQ + 256 * KP2 * 2;     // phase A: KVstate lives here
    const uint32_t sV = sK + 256 * KP2 * 2;
    const uint32_t sP = sV + 256 * KP2 * 2;

    const int b = blockIdx.x;
    const int h = blockIdx.y;
    const float s = slope[h];

    const int t = threadIdx.x;
    const int w = t >> 5, lane = t & 31;
    const int r = lane >> 2, q = lane & 3;
    const int lrow = (lane & 7) + ((lane >> 3) & 1) * 8;
    const int lcol = (lane >> 4) * 8;
    const int trow = (lane & 7) + ((lane >> 4) & 1) * 8;
    const int tcol = ((lane >> 3) & 1) * 8;

    const __half* qkv = g_qkvh + (size_t)(b * BLK) * QKVW + h * 384;
    const __half* kvst = g_kvsth + (size_t)(h * NB + b) * HD * HD;

    __half* Qs = (__half*)osm;
    __half* KVs = Qs + 256 * KP2;               // == K slot

    // ---- Phase A staging: Q (256x128) + KVstate (128x128) ----
#pragma unroll
    for (int it = 0; it < 16; ++it) {
        int id = t + 256 * it;
        int row = id >> 4, c16 = id & 15;
        *(uint4*)&Qs[row * KP2 + c16 * 8] = *(const uint4*)(qkv + (size_t)row * QKVW + c16 * 8);
    }
#pragma unroll
    for (int it = 0; it < 8; ++it) {
        int id = t + 256 * it;                  // 0..2047
        int row = id >> 4, c16 = id & 15;       // 128 rows x 16 chunks
        *(uint4*)&KVs[row * KP2 + c16 * 8] = *(const uint4*)(kvst + (size_t)row * HD + c16 * 8);
    }
    __syncthreads();

    // ---- Phase A compute: oc[tt] = qdec .* (q @ KV) for m-tiles {w, 15-w} ----
    float oc[2][16][4];
#pragma unroll
    for (int tt = 0; tt < 2; ++tt) {
        const int mt = (tt == 0) ? w : (15 - w);
#pragma unroll
        for (int j = 0; j < 16; ++j)
#pragma unroll
            for (int p = 0; p < 4; ++p) oc[tt][j][p] = 0.0f;

#pragma unroll
        for (int kc = 0; kc < 8; ++kc) {
            uint32_t qa[4], bf[16][2];
            ldsm_x4(qa[0], qa[1], qa[2], qa[3],
                    sQ + ((mt * 16 + lrow) * KP2 + kc * 16 + lcol) * 2);
#pragma unroll
            for (int jj = 0; jj < 8; ++jj) {
                ldsm_x4_t(bf[2 * jj][0], bf[2 * jj + 1][0],
                          bf[2 * jj][1], bf[2 * jj + 1][1],
                          sK + ((kc * 16 + trow) * KP2 + jj * 16 + tcol) * 2);
            }
#pragma unroll
            for (int j = 0; j < 16; ++j) mma_f16(oc[tt][j], qa, bf[j]);
        }

        // exact qdec scaling on fp32 accumulator
        const int mrow = mt * 16 + r;
        const float qd0 = expf(-s * (float)(mrow + 1));
        const float qd8 = expf(-s * (float)(mrow + 9));
#pragma unroll
        for (int j = 0; j < 16; ++j) {
            oc[tt][j][0] *= qd0; oc[tt][j][1] *= qd0;
            oc[tt][j][2] *= qd8; oc[tt][j][3] *= qd8;
        }
    }
    __syncthreads();   // all warps done reading KVstate before K overwrites it

    // ---- Phase B staging: K (into KV slot) + V ----
    __half* Ks = KVs;
    __half* Vs = Ks + 256 * KP2;
#pragma unroll
    for (int it = 0; it < 16; ++it) {
        int id = t + 256 * it;
        int row = id >> 4, c16 = id & 15;
        *(uint4*)&Ks[row * KP2 + c16 * 8] = *(const uint4*)(qkv + 128 + (size_t)row * QKVW + c16 * 8);
        *(uint4*)&Vs[row * KP2 + c16 * 8] = *(const uint4*)(qkv + 256 + (size_t)row * QKVW + c16 * 8);
    }
    __syncthreads();

    const uint32_t sPw = sP + w * 16 * PSTR * 2;
    __half* Pw = (__half*)(osm) + (sPw - sQ) / 2;

#pragma unroll
    for (int tt = 0; tt < 2; ++tt) {
        const int mt = (tt == 0) ? w : (15 - w);
        const int mrow = mt * 16 + r;

        const int nchunks = mt / 4 + 1;
        for (int nt = 0; nt < nchunks; ++nt) {
            float pc[8][4];
#pragma unroll
            for (int j = 0; j < 8; ++j)
#pragma unroll
                for (int p = 0; p < 4; ++p) pc[j][p] = 0.0f;

#pragma unroll
            for (int kc = 0; kc < 8; ++kc) {
                uint32_t qa[4], kb[8][2];
                ldsm_x4(qa[0], qa[1], qa[2], qa[3],
                        sQ + ((mt * 16 + lrow) * KP2 + kc * 16 + lcol) * 2);
#pragma unroll
                for (int j16 = 0; j16 < 4; ++j16) {
                    ldsm_x4(kb[2 * j16][0], kb[2 * j16 + 1][0],
                            kb[2 * j16][1], kb[2 * j16 + 1][1],
                            sK + ((nt * 64 + j16 * 16 + lrow) * KP2 + kc * 16 + lcol) * 2);
                }
#pragma unroll
                for (int j = 0; j < 8; ++j) mma_f16(pc[j], qa, kb[j]);
            }

#pragma unroll
            for (int j = 0; j < 8; ++j) {
                const int n0 = nt * 64 + j * 8 + 2 * q;
                float f0 = (mrow >= n0)         ? pc[j][0] * expf(-s * (float)(mrow - n0))         : 0.0f;
                float f1 = (mrow >= n0 + 1)     ? pc[j][1] * expf(-s * (float)(mrow - n0 - 1))     : 0.0f;
                float f2 = (mrow + 8 >= n0)     ? pc[j][2] * expf(-s * (float)(mrow + 8 - n0))     : 0.0f;
                float f3 = (mrow + 8 >= n0 + 1) ? pc[j][3] * expf(-s * (float)(mrow + 8 - n0 - 1)) : 0.0f;
                __half2 h0 = __floats2half2_rn(f0, f1);
                __half2 h1 = __floats2half2_rn(f2, f3);
                *(__half2*)&Pw[r * PSTR + j * 8 + 2 * q]       = h0;
                *(__half2*)&Pw[(r + 8) * PSTR + j * 8 + 2 * q] = h1;
            }
            __syncwarp();

#pragma unroll
            for (int ks = 0; ks < 4; ++ks) {
                uint32_t pa[4], vb[16][2];
                ldsm_x4(pa[0], pa[1], pa[2], pa[3],
                        sPw + (lrow * PSTR + ks * 16 + lcol) * 2);
#pragma unroll
                for (int jj = 0; jj < 8; ++jj) {
                    ldsm_x4_t(vb[2 * jj][0], vb[2 * jj + 1][0],
                              vb[2 * jj][1], vb[2 * jj + 1][1],
                              sV + ((nt * 64 + ks * 16 + trow) * KP2 + jj * 16 + tcol) * 2);
                }
#pragma unroll
                for (int j = 0; j < 16; ++j) mma_f16(oc[tt][j], pa, vb[j]);
            }
            __syncwarp();
        }

        // single plain store (no RMW)
        float* hb = g_hidden + (size_t)(b * BLK + mt * 16) * INNER + h * HD;
#pragma unroll
        for (int j = 0; j < 16; ++j) {
            const int e = j * 8 + 2 * q;
            *(float2*)(hb + (size_t)r * INNER + e)       = make_float2(oc[tt][j][0], oc[tt][j][1]);
            *(float2*)(hb + (size_t)(r + 8) * INNER + e) = make_float2(oc[tt][j][2], oc[tt][j][3]);
        }
    }
}

// ---------------- RMSNorm * weight * gate(fp16) -> fp16 ----------------
__global__ __launch_bounds__(256)
void rmsnorm_gate(const float* __restrict__ nw)
{
    const int m = blockIdx.x;
    const int t = threadIdx.x;
    const float* hrow = g_hidden + (size_t)m * INNER;
    const __half* grow = g_gateh + (size_t)m * INNER;
    __half* orow = g_ghalf + (size_t)m * INNER;

    float ss = 0.0f;
    for (int i = t; i < INNER / 4; i += 256) {
        float4 h4 = *(const float4*)(hrow + i * 4);
        ss += h4.x * h4.x + h4.y * h4.y + h4.z * h4.z + h4.w * h4.w;
    }
    __shared__ float red[256];
    red[t] = ss;
    __syncthreads();
    for (int s2 = 128; s2 > 0; s2 >>= 1) {
        if (t < s2) red[t] += red[t + s2];
        __syncthreads();
    }
    const float rs = rsqrtf(red[0] / (float)INNER + EPS_RMS);

    for (int i = t; i < INNER / 4; i += 256) {
        float4 h4 = *(const float4*)(hrow + i * 4);
        uint2 g2 = *(const uint2*)(grow + i * 4);
        float2 g0 = __half22float2(*(__half2*)&g2.x);
        float2 g1 = __half22float2(*(__half2*)&g2.y);
        float4 w4 = *(const float4*)(nw + i * 4);
        __half2 o0 = __floats2half2_rn(g0.x * (h4.x * rs * w4.x),
                                       g0.y * (h4.y * rs * w4.y));
        __half2 o1 = __floats2half2_rn(g1.x * (h4.z * rs * w4.z),
                                       g1.y * (h4.w * rs * w4.w));
        uint2 o;
        o.x = *(uint32_t*)&o0; o.y = *(uint32_t*)&o1;
        *(uint2*)(orow + i * 4) = o;
    }
}

// ---------------- launcher ----------------
extern "C" void kernel_launch(void* const* d_in, const int* in_sizes, int n_in,
                              void* d_out, int out_size)
{
    (void)in_sizes; (void)n_in; (void)out_size;
    const float* x     = (const float*)d_in[0];
    const float* wqkv  = (const float*)d_in[1];
    const float* wgate = (const float*)d_in[2];
    const float* wout  = (const float*)d_in[3];
    const float* nw    = (const float*)d_in[4];
    const float* kvc   = (const float*)d_in[5];
    const float* slope = (const float*)d_in[6];
    float* out = (float*)d_out;

    __half *p_xh = nullptr, *p_wqkvh = nullptr, *p_wgateh = nullptr,
           *p_wouth = nullptr, *p_ghalf = nullptr;
    cudaGetSymbolAddress((void**)&p_xh, g_xh);
    cudaGetSymbolAddress((void**)&p_wqkvh, g_wqkvh);
    cudaGetSymbolAddress((void**)&p_wgateh, g_wgateh);
    cudaGetSymbolAddress((void**)&p_wouth, g_wouth);
    cudaGetSymbolAddress((void**)&p_ghalf, g_ghalf);

    cudaFuncSetAttribute((const void*)gemm_qkvgate, cudaFuncAttributeMaxDynamicSharedMemorySize, GEMM_SMEM);
    cudaFuncSetAttribute((const void*)gemm_out,     cudaFuncAttributeMaxDynamicSharedMemorySize, GEMM_SMEM);
    cudaFuncSetAttribute((const void*)attn_out_mma, cudaFuncAttributeMaxDynamicSharedMemorySize, ATTNOUT_SMEM);

    // all fp32 -> fp16 conversions in one launch
    cvt_all_kernel<<<(N1 + N2 + N3 + N4) / 256, 256>>>(x, wqkv, wgate, wout,
                                                       p_xh, p_wqkvh, p_wgateh, p_wouth);

    // fused: qkv = silu(x@wqkv^T) -> fp16 ; gate = sigmoid(x@wgate^T) -> fp16
    gemm_qkvgate<<<dim3((QKVW + INNER) / BN, SEQ / BM), NTHR, GEMM_SMEM>>>(p_xh, p_wqkvh, p_wgateh);

    // lightning attention
    attn_kvblocks_mma<<<dim3(NB, NH), 128>>>(slope);
    attn_scan<<<(NH * HD * HD) / 256, 256>>>(kvc, slope);
    attn_out_mma<<<dim3(NB, NH), 256, ATTNOUT_SMEM>>>(slope);

    // rmsnorm * weight * gate -> fp16
    rmsnorm_gate<<<SEQ, 256>>>(nw);

    // out = (gate * normed) @ w_out^T
    gemm_out<<<dim3(HDIM / BN, SEQ / BM), NTHR, GEMM_SMEM>>>(p_ghalf, p_wouth, out);
}